// round 1
// baseline (speedup 1.0000x reference)
#include <cuda_runtime.h>
#include <cstddef>

#define N_NODES 100000
#define FANOUT  16

// Scratch: SP = [S | P] per layer (max N x 256 fp32), H = hidden (N x 128 fp32).
__device__ float g_SP[(size_t)N_NODES * 256];
__device__ float g_H [(size_t)N_NODES * 128];

// ---------------------------------------------------------------------------
// GEMM: C[:, y*OUT : (y+1)*OUT] = A[M,K] @ W[:, y*K : (y+1)*K]^T
// W is [OUT, 2K] row-major. blockIdx.y = 0 -> self half (S), 1 -> neigh half (P).
// C is [M, 2*OUT] row-major.
// ---------------------------------------------------------------------------
template<int K, int OUT>
__global__ void gemm_sp(const float* __restrict__ A, const float* __restrict__ W,
                        float* __restrict__ C, int M) {
    constexpr int BM = 128;
    constexpr int BN = (OUT >= 128 ? 128 : OUT);
    constexpr int BK = 16;
    constexpr int TM = 8, TN = 8;
    constexpr int THREADS = (BM / TM) * (BN / TN);   // 256 (OUT=128) or 128 (OUT=64)

    __shared__ float As[BK][BM];
    __shared__ float Bs[BK][BN];

    const int m0  = blockIdx.x * BM;
    const float* Wb = W + (size_t)blockIdx.y * K;    // row stride 2K
    const int tid = threadIdx.x;
    const int tc  = tid % (BN / TN);                 // n-direction
    const int tr  = tid / (BN / TN);                 // m-direction

    float acc[TM][TN] = {};

    for (int k0 = 0; k0 < K; k0 += BK) {
        // Load A tile (BM x BK), transposed into As[k][m]
        #pragma unroll
        for (int i = tid; i < BM * BK / 4; i += THREADS) {
            int r = i / (BK / 4);
            int c = (i % (BK / 4)) * 4;
            float4 v = make_float4(0.f, 0.f, 0.f, 0.f);
            if (m0 + r < M)
                v = *(const float4*)(A + (size_t)(m0 + r) * K + k0 + c);
            As[c + 0][r] = v.x; As[c + 1][r] = v.y;
            As[c + 2][r] = v.z; As[c + 3][r] = v.w;
        }
        // Load B tile (BN x BK) from W rows, transposed into Bs[k][n]
        #pragma unroll
        for (int i = tid; i < BN * BK / 4; i += THREADS) {
            int r = i / (BK / 4);
            int c = (i % (BK / 4)) * 4;
            float4 v = *(const float4*)(Wb + (size_t)r * (2 * K) + k0 + c);
            Bs[c + 0][r] = v.x; Bs[c + 1][r] = v.y;
            Bs[c + 2][r] = v.z; Bs[c + 3][r] = v.w;
        }
        __syncthreads();

        #pragma unroll
        for (int k = 0; k < BK; k++) {
            float ar[TM], br[TN];
            #pragma unroll
            for (int t = 0; t < TM; t += 4)
                *(float4*)&ar[t] = *(const float4*)&As[k][tr * TM + t];
            #pragma unroll
            for (int t = 0; t < TN; t += 4)
                *(float4*)&br[t] = *(const float4*)&Bs[k][tc * TN + t];
            #pragma unroll
            for (int a = 0; a < TM; a++)
                #pragma unroll
                for (int b = 0; b < TN; b++)
                    acc[a][b] += ar[a] * br[b];
        }
        __syncthreads();
    }

    const int cb = blockIdx.y * OUT + tc * TN;
    #pragma unroll
    for (int a = 0; a < TM; a++) {
        int m = m0 + tr * TM + a;
        if (m < M) {
            #pragma unroll
            for (int b = 0; b < TN; b += 4)
                *(float4*)(C + (size_t)m * (2 * OUT) + cb + b) = *(const float4*)&acc[a][b];
        }
    }
}

// ---------------------------------------------------------------------------
// Aggregation: out[r, :] = relu( S[node] + (1/16) * sum_j P[neigh[node][j]] )
// SP layout: [M, 2*OUT], S = cols [0,OUT), P = cols [OUT, 2*OUT).
// One warp per output row. If USE_NODES, node = nodes[r], else node = r.
// ---------------------------------------------------------------------------
template<int OUT, bool USE_NODES>
__global__ void agg_kernel(const float* __restrict__ SP, const int* __restrict__ neigh,
                           const int* __restrict__ nodes, float* __restrict__ out, int M) {
    const int w    = (blockIdx.x * blockDim.x + threadIdx.x) >> 5;
    const int lane = threadIdx.x & 31;
    if (w >= M) return;

    const int node = USE_NODES ? nodes[w] : w;

    int nid = 0;
    if (lane < FANOUT) nid = neigh[(size_t)node * FANOUT + lane];

    constexpr int V = OUT / 32;          // floats per lane (4 or 2)
    float acc[V] = {};

    #pragma unroll
    for (int j = 0; j < FANOUT; j++) {
        int nj = __shfl_sync(0xffffffffu, nid, j);
        const float* p = SP + (size_t)nj * (2 * OUT) + OUT + lane * V;
        if constexpr (V == 4) {
            float4 v = *(const float4*)p;
            acc[0] += v.x; acc[1] += v.y; acc[2] += v.z; acc[3] += v.w;
        } else {
            float2 v = *(const float2*)p;
            acc[0] += v.x; acc[1] += v.y;
        }
    }

    const float* s = SP + (size_t)node * (2 * OUT) + lane * V;
    float*       o = out + (size_t)w * OUT + lane * V;
    constexpr float inv = 1.0f / (float)FANOUT;

    if constexpr (V == 4) {
        float4 sv = *(const float4*)s;
        float4 r;
        r.x = fmaxf(fmaf(acc[0], inv, sv.x), 0.f);
        r.y = fmaxf(fmaf(acc[1], inv, sv.y), 0.f);
        r.z = fmaxf(fmaf(acc[2], inv, sv.z), 0.f);
        r.w = fmaxf(fmaf(acc[3], inv, sv.w), 0.f);
        *(float4*)o = r;
    } else {
        float2 sv = *(const float2*)s;
        float2 r;
        r.x = fmaxf(fmaf(acc[0], inv, sv.x), 0.f);
        r.y = fmaxf(fmaf(acc[1], inv, sv.y), 0.f);
        *(float2*)o = r;
    }
}

// ---------------------------------------------------------------------------

extern "C" void kernel_launch(void* const* d_in, const int* in_sizes, int n_in,
                              void* d_out, int out_size) {
    const float* features = (const float*)d_in[0];   // [N, 256]
    const float* W1       = (const float*)d_in[1];   // [128, 512]
    const float* W2       = (const float*)d_in[2];   // [128, 256]
    const float* W3       = (const float*)d_in[3];   // [128, 256]
    const float* W4       = (const float*)d_in[4];   // [64, 256]
    const int*   nodes    = (const int*)d_in[5];     // [N]
    const int*   neigh    = (const int*)d_in[6];     // [N, 16]
    float*       out      = (float*)d_out;           // [N, 64]

    const int M = in_sizes[5];                       // number of nodes

    float *sp, *h;
    cudaGetSymbolAddress((void**)&sp, g_SP);
    cudaGetSymbolAddress((void**)&h,  g_H);

    dim3 gemm_grid((M + 127) / 128, 2);
    int agg_blocks = (M + 7) / 8;                    // 8 warps (rows) per 256-thread block

    // Layer 1: features[N,256] -> SP[N,256] -> H[N,128]
    gemm_sp<256, 128><<<gemm_grid, 256>>>(features, W1, sp, M);
    agg_kernel<128, false><<<agg_blocks, 256>>>(sp, neigh, nullptr, h, M);

    // Layer 2
    gemm_sp<128, 128><<<gemm_grid, 256>>>(h, W2, sp, M);
    agg_kernel<128, false><<<agg_blocks, 256>>>(sp, neigh, nullptr, h, M);

    // Layer 3
    gemm_sp<128, 128><<<gemm_grid, 256>>>(h, W3, sp, M);
    agg_kernel<128, false><<<agg_blocks, 256>>>(sp, neigh, nullptr, h, M);

    // Layer 4: H[N,128] -> SP[N,128] -> out[N,64] (final gather honors `nodes`)
    gemm_sp<128, 64><<<gemm_grid, 128>>>(h, W4, sp, M);
    agg_kernel<64, true><<<agg_blocks, 256>>>(sp, neigh, nodes, out, M);
}

// round 2
// speedup vs baseline: 1.6177x; 1.6177x over previous
#include <cuda_runtime.h>
#include <cuda_bf16.h>
#include <cstdint>
#include <cstddef>

#define N_NODES 100000
#define FANOUT  16

// Scratch: SP = [S | P] per layer (max N x 256 fp32), H = hidden (N x 128 fp32).
__device__ float g_SP[(size_t)N_NODES * 256];
__device__ float g_H [(size_t)N_NODES * 128];

// ---------------------------------------------------------------------------
// Tensor-core GEMM with 2-way bf16 split (3 MMAs: hh + hl + lh).
// C[:, y*OUT : (y+1)*OUT] = A[M,K] @ W[:, y*K : (y+1)*K]^T
// W is [OUT, 2K] row-major. C is [M, 2*OUT] row-major.
// Block: 256 threads = 8 warps (2 m-warps x 4 n-warps). BM=128, BN=OUT, BK=32.
// ---------------------------------------------------------------------------

__device__ __forceinline__ void mma16816(float c[4], const uint32_t a[4], const uint32_t b[2]) {
    asm volatile(
        "mma.sync.aligned.m16n8k16.row.col.f32.bf16.bf16.f32 "
        "{%0,%1,%2,%3}, {%4,%5,%6,%7}, {%8,%9}, {%0,%1,%2,%3};\n"
        : "+f"(c[0]), "+f"(c[1]), "+f"(c[2]), "+f"(c[3])
        : "r"(a[0]), "r"(a[1]), "r"(a[2]), "r"(a[3]), "r"(b[0]), "r"(b[1]));
}

template<int K, int OUT>
__global__ __launch_bounds__(256)
void gemm_tc(const float* __restrict__ A, const float* __restrict__ W,
             float* __restrict__ C, int M) {
    constexpr int BM = 128;
    constexpr int BN = OUT;             // 128 or 64
    constexpr int BK = 32;
    constexpr int STRIDE = BK + 8;      // bf16 elems; 80B row stride -> conflict-free frags
    constexpr int NFRAG = BN / 32;      // n8-frags per warp (4 or 2)
    constexpr int NT = 2 * OUT;         // C row width

    __shared__ __nv_bfloat16 Ah[BM * STRIDE], Al[BM * STRIDE];
    __shared__ __nv_bfloat16 Bh[BN * STRIDE], Bl[BN * STRIDE];

    const int tid  = threadIdx.x;
    const int wid  = tid >> 5;
    const int lane = tid & 31;
    const int g    = lane >> 2;         // group 0..7
    const int tig  = lane & 3;          // thread-in-group
    const int wm   = wid & 1;           // m-warp (0..1) -> 64 rows each
    const int wn   = wid >> 1;          // n-warp (0..3) -> BN/4 cols each

    const int m0 = blockIdx.x * BM;
    const float* Wb = W + (size_t)blockIdx.y * K;   // row stride 2K

    float acc[4][NFRAG][4] = {};        // [mfrag][nfrag][c0..c3]

    const uint32_t* pAh = (const uint32_t*)Ah;
    const uint32_t* pAl = (const uint32_t*)Al;
    const uint32_t* pBh = (const uint32_t*)Bh;
    const uint32_t* pBl = (const uint32_t*)Bl;
    constexpr int S2 = STRIDE / 2;      // uint32 row stride (= 20)

    for (int k0 = 0; k0 < K; k0 += BK) {
        // ---- Load + split A tile: BM x BK floats ----
        #pragma unroll
        for (int i = tid; i < BM * (BK / 4); i += 256) {
            int r = i >> 3;
            int c = (i & 7) * 4;
            float4 v = make_float4(0.f, 0.f, 0.f, 0.f);
            if (m0 + r < M)
                v = *(const float4*)(A + (size_t)(m0 + r) * K + k0 + c);
            float vv[4] = {v.x, v.y, v.z, v.w};
            #pragma unroll
            for (int j = 0; j < 4; j++) {
                __nv_bfloat16 hi = __float2bfloat16(vv[j]);
                __nv_bfloat16 lo = __float2bfloat16(vv[j] - __bfloat162float(hi));
                Ah[r * STRIDE + c + j] = hi;
                Al[r * STRIDE + c + j] = lo;
            }
        }
        // ---- Load + split B tile: BN x BK floats from W rows ----
        #pragma unroll
        for (int i = tid; i < BN * (BK / 4); i += 256) {
            int r = i >> 3;
            int c = (i & 7) * 4;
            float4 v = *(const float4*)(Wb + (size_t)r * (2 * K) + k0 + c);
            float vv[4] = {v.x, v.y, v.z, v.w};
            #pragma unroll
            for (int j = 0; j < 4; j++) {
                __nv_bfloat16 hi = __float2bfloat16(vv[j]);
                __nv_bfloat16 lo = __float2bfloat16(vv[j] - __bfloat162float(hi));
                Bh[r * STRIDE + c + j] = hi;
                Bl[r * STRIDE + c + j] = lo;
            }
        }
        __syncthreads();

        #pragma unroll
        for (int kk = 0; kk < BK; kk += 16) {
            const int kb = kk / 2 + tig;   // uint32 col offset within row
            // B fragments for all n-frags (hi + lo)
            uint32_t bh[NFRAG][2], bl[NFRAG][2];
            #pragma unroll
            for (int ni = 0; ni < NFRAG; ni++) {
                int row = wn * (BN / 4) + ni * 8 + g;
                int base = row * S2 + kb;
                bh[ni][0] = pBh[base];     bh[ni][1] = pBh[base + 4];
                bl[ni][0] = pBl[base];     bl[ni][1] = pBl[base + 4];
            }
            #pragma unroll
            for (int mi = 0; mi < 4; mi++) {
                int row = wm * 64 + mi * 16 + g;
                int base = row * S2 + kb;
                uint32_t ah[4], al[4];
                ah[0] = pAh[base];             ah[1] = pAh[base + 8 * S2];
                ah[2] = pAh[base + 4];         ah[3] = pAh[base + 8 * S2 + 4];
                al[0] = pAl[base];             al[1] = pAl[base + 8 * S2];
                al[2] = pAl[base + 4];         al[3] = pAl[base + 8 * S2 + 4];
                #pragma unroll
                for (int ni = 0; ni < NFRAG; ni++) {
                    mma16816(acc[mi][ni], ah, bh[ni]);   // hi*hi
                    mma16816(acc[mi][ni], ah, bl[ni]);   // hi*lo
                    mma16816(acc[mi][ni], al, bh[ni]);   // lo*hi
                }
            }
        }
        __syncthreads();
    }

    // ---- Epilogue ----
    const int colbase = blockIdx.y * OUT + wn * (BN / 4);
    #pragma unroll
    for (int mi = 0; mi < 4; mi++) {
        int r0 = m0 + wm * 64 + mi * 16 + g;
        #pragma unroll
        for (int ni = 0; ni < NFRAG; ni++) {
            int c = colbase + ni * 8 + tig * 2;
            if (r0 < M)
                *(float2*)(C + (size_t)r0 * NT + c) =
                    make_float2(acc[mi][ni][0], acc[mi][ni][1]);
            if (r0 + 8 < M)
                *(float2*)(C + (size_t)(r0 + 8) * NT + c) =
                    make_float2(acc[mi][ni][2], acc[mi][ni][3]);
        }
    }
}

// ---------------------------------------------------------------------------
// Aggregation: out[r, :] = relu( S[node] + (1/16) * sum_j P[neigh[node][j]] )
// SP layout: [M, 2*OUT], S = cols [0,OUT), P = cols [OUT, 2*OUT).
// One warp per output row.
// ---------------------------------------------------------------------------
template<int OUT, bool USE_NODES>
__global__ void agg_kernel(const float* __restrict__ SP, const int* __restrict__ neigh,
                           const int* __restrict__ nodes, float* __restrict__ out, int M) {
    const int w    = (blockIdx.x * blockDim.x + threadIdx.x) >> 5;
    const int lane = threadIdx.x & 31;
    if (w >= M) return;

    const int node = USE_NODES ? nodes[w] : w;

    int nid = 0;
    if (lane < FANOUT) nid = neigh[(size_t)node * FANOUT + lane];

    constexpr int V = OUT / 32;          // floats per lane (4 or 2)
    float acc[V] = {};

    #pragma unroll
    for (int j = 0; j < FANOUT; j++) {
        int nj = __shfl_sync(0xffffffffu, nid, j);
        const float* p = SP + (size_t)nj * (2 * OUT) + OUT + lane * V;
        if constexpr (V == 4) {
            float4 v = *(const float4*)p;
            acc[0] += v.x; acc[1] += v.y; acc[2] += v.z; acc[3] += v.w;
        } else {
            float2 v = *(const float2*)p;
            acc[0] += v.x; acc[1] += v.y;
        }
    }

    const float* s = SP + (size_t)node * (2 * OUT) + lane * V;
    float*       o = out + (size_t)w * OUT + lane * V;
    constexpr float inv = 1.0f / (float)FANOUT;

    if constexpr (V == 4) {
        float4 sv = *(const float4*)s;
        float4 r;
        r.x = fmaxf(fmaf(acc[0], inv, sv.x), 0.f);
        r.y = fmaxf(fmaf(acc[1], inv, sv.y), 0.f);
        r.z = fmaxf(fmaf(acc[2], inv, sv.z), 0.f);
        r.w = fmaxf(fmaf(acc[3], inv, sv.w), 0.f);
        *(float4*)o = r;
    } else {
        float2 sv = *(const float2*)s;
        float2 r;
        r.x = fmaxf(fmaf(acc[0], inv, sv.x), 0.f);
        r.y = fmaxf(fmaf(acc[1], inv, sv.y), 0.f);
        *(float2*)o = r;
    }
}

// ---------------------------------------------------------------------------

extern "C" void kernel_launch(void* const* d_in, const int* in_sizes, int n_in,
                              void* d_out, int out_size) {
    const float* features = (const float*)d_in[0];   // [N, 256]
    const float* W1       = (const float*)d_in[1];   // [128, 512]
    const float* W2       = (const float*)d_in[2];   // [128, 256]
    const float* W3       = (const float*)d_in[3];   // [128, 256]
    const float* W4       = (const float*)d_in[4];   // [64, 256]
    const int*   nodes    = (const int*)d_in[5];     // [N]
    const int*   neigh    = (const int*)d_in[6];     // [N, 16]
    float*       out      = (float*)d_out;           // [N, 64]

    const int M = in_sizes[5];

    float *sp, *h;
    cudaGetSymbolAddress((void**)&sp, g_SP);
    cudaGetSymbolAddress((void**)&h,  g_H);

    dim3 gemm_grid((M + 127) / 128, 2);
    int agg_blocks = (M + 7) / 8;                    // 8 warps (rows) per 256-thread block

    // Layer 1: features[N,256] -> SP[N,256] -> H[N,128]
    gemm_tc<256, 128><<<gemm_grid, 256>>>(features, W1, sp, M);
    agg_kernel<128, false><<<agg_blocks, 256>>>(sp, neigh, nullptr, h, M);

    // Layer 2
    gemm_tc<128, 128><<<gemm_grid, 256>>>(h, W2, sp, M);
    agg_kernel<128, false><<<agg_blocks, 256>>>(sp, neigh, nullptr, h, M);

    // Layer 3
    gemm_tc<128, 128><<<gemm_grid, 256>>>(h, W3, sp, M);
    agg_kernel<128, false><<<agg_blocks, 256>>>(sp, neigh, nullptr, h, M);

    // Layer 4: H[N,128] -> SP[N,128] -> out[N,64] (final gather honors `nodes`)
    gemm_tc<128, 64><<<gemm_grid, 256>>>(h, W4, sp, M);
    agg_kernel<64, true><<<agg_blocks, 256>>>(sp, neigh, nodes, out, M);
}

// round 7
// speedup vs baseline: 2.2019x; 1.3611x over previous
#include <cuda_runtime.h>
#include <cuda_bf16.h>
#include <cstdint>
#include <cstddef>

#define N_NODES 100000
#define FANOUT  16

// Global scratch
__device__ float g_SP[(size_t)N_NODES * 256];
__device__ __align__(16) __nv_bfloat16 g_Ahi[(size_t)N_NODES * 256];
__device__ __align__(16) __nv_bfloat16 g_Alo[(size_t)N_NODES * 256];
// Packed weights (B-operand layout [2*OUT, K]), hi/lo
#define WOFF1 0
#define WOFF2 65536
#define WOFF3 98304
#define WOFF4 131072
__device__ __align__(16) __nv_bfloat16 g_Bhi[147456];
__device__ __align__(16) __nv_bfloat16 g_Blo[147456];

// ---------------------------------------------------------------------------
// Helpers
// ---------------------------------------------------------------------------
__device__ __forceinline__ uint32_t smem_u32(const void* p) {
    return (uint32_t)__cvta_generic_to_shared(p);
}
__device__ __forceinline__ void cp16(uint32_t dst, const void* src, int sz) {
    asm volatile("cp.async.cg.shared.global [%0], [%1], 16, %2;\n"
                 :: "r"(dst), "l"(src), "r"(sz));
}
__device__ __forceinline__ void ldsm_x4(uint32_t& r0, uint32_t& r1, uint32_t& r2,
                                        uint32_t& r3, uint32_t addr) {
    asm volatile("ldmatrix.sync.aligned.m8n8.x4.shared.b16 {%0,%1,%2,%3}, [%4];"
                 : "=r"(r0), "=r"(r1), "=r"(r2), "=r"(r3) : "r"(addr));
}
__device__ __forceinline__ void mma16816(float c[4], const uint32_t a[4], const uint32_t b[2]) {
    asm volatile(
        "mma.sync.aligned.m16n8k16.row.col.f32.bf16.bf16.f32 "
        "{%0,%1,%2,%3}, {%4,%5,%6,%7}, {%8,%9}, {%0,%1,%2,%3};\n"
        : "+f"(c[0]), "+f"(c[1]), "+f"(c[2]), "+f"(c[3])
        : "r"(a[0]), "r"(a[1]), "r"(a[2]), "r"(a[3]), "r"(b[0]), "r"(b[1]));
}

// ---------------------------------------------------------------------------
// bf16-split tensor GEMM (3 MMAs: hh + hl + lh).
// C[:, by*128 : by*128+128] = [Ahi+Alo][M,K] @ [Bhi+Blo][by*128.., K]^T
// BM=128, BN=128, BK=32, cp.async double-buffered, ldmatrix frag loads.
// SMEM rows: 32 bf16 = 64B, SW64 swizzle (off ^ ((off>>3)&0x30)).
// ---------------------------------------------------------------------------
template<int K, int NT>
__global__ __launch_bounds__(256)
void gemm_mma(const __nv_bfloat16* __restrict__ Ahi, const __nv_bfloat16* __restrict__ Alo,
              const __nv_bfloat16* __restrict__ Bhi, const __nv_bfloat16* __restrict__ Blo,
              float* __restrict__ C, int M) {
    constexpr int NC    = K / 32;           // k-chunks
    constexpr int TSZ   = 128 * 64;         // bytes per tile (128 rows x 64B)
    constexpr int STAGE = 4 * TSZ;          // Ah, Al, Bh, Bl

    extern __shared__ char dsm[];
    const uint32_t base = (smem_u32(dsm) + 127u) & ~127u;

    const int tid  = threadIdx.x;
    const int wid  = tid >> 5;
    const int lane = tid & 31;
    const int g    = lane >> 2;
    const int tig  = lane & 3;
    const int wm   = wid & 1;               // m half (64 rows)
    const int wn   = wid >> 1;              // n quarter (32 cols)
    const int m0   = blockIdx.x * 128;

    const __nv_bfloat16* Bh = Bhi + (size_t)blockIdx.y * 128 * K;
    const __nv_bfloat16* Bl = Blo + (size_t)blockIdx.y * 128 * K;

    // ldmatrix per-lane address components (within a 128x32 tile, 64B rows)
    // A: mats = (r, cb), (r+8, cb), (r, cb+16), (r+8, cb+16)
    const int arow_add = ((lane >> 3) & 1) * 8;
    const int acol_add = ((lane >> 4) & 1) * 16;
    // B: mats = (n, cb), (n, cb+16), (n+8, cb), (n+8, cb+16)
    const int brow_add = ((lane >> 4) & 1) * 8;
    const int bcol_add = ((lane >> 3) & 1) * 16;

    uint32_t abase[4], asw[4];
    #pragma unroll
    for (int mi = 0; mi < 4; mi++) {
        int r = wm * 64 + mi * 16 + arow_add + (lane & 7);
        abase[mi] = r * 64;
        asw[mi]   = ((r >> 1) & 3) << 4;
    }
    uint32_t bbase[2], bsw[2];
    #pragma unroll
    for (int np = 0; np < 2; np++) {
        int r = wn * 32 + np * 16 + brow_add + (lane & 7);
        bbase[np] = r * 64;
        bsw[np]   = ((r >> 1) & 3) << 4;
    }

    auto load_chunk = [&](int kc, int s) {
        const uint32_t sb = base + s * STAGE;
        #pragma unroll
        for (int u = tid; u < 512; u += 256) {
            int row = u >> 2, c16 = u & 3;
            uint32_t off = row * 64 + ((c16 ^ ((row >> 1) & 3)) << 4);
            int gr = m0 + row;
            int szA = (gr < M) ? 16 : 0;
            size_t giA = (size_t)gr * K + kc * 32 + c16 * 8;
            size_t giB = (size_t)row * K + kc * 32 + c16 * 8;
            cp16(sb + off,            Ahi + giA, szA);
            cp16(sb + TSZ + off,      Alo + giA, szA);
            cp16(sb + 2 * TSZ + off,  Bh + giB, 16);
            cp16(sb + 3 * TSZ + off,  Bl + giB, 16);
        }
        asm volatile("cp.async.commit_group;" ::: "memory");
    };

    float acc[4][4][4] = {};                // [mi][ni][c]

    load_chunk(0, 0);

    for (int kc = 0; kc < NC; kc++) {
        const int s = kc & 1;
        if (kc + 1 < NC) {
            load_chunk(kc + 1, s ^ 1);
            asm volatile("cp.async.wait_group 1;" ::: "memory");
        } else {
            asm volatile("cp.async.wait_group 0;" ::: "memory");
        }
        __syncthreads();

        const uint32_t sAh = base + s * STAGE;
        const uint32_t sAl = sAh + TSZ;
        const uint32_t sBh = sAh + 2 * TSZ;
        const uint32_t sBl = sAh + 3 * TSZ;

        #pragma unroll
        for (int ks = 0; ks < 2; ks++) {
            uint32_t bh[4][2], bl[4][2];
            #pragma unroll
            for (int np = 0; np < 2; np++) {
                uint32_t off = bbase[np] + ((uint32_t)(ks * 32 + bcol_add) ^ bsw[np]);
                ldsm_x4(bh[np*2][0], bh[np*2][1], bh[np*2+1][0], bh[np*2+1][1], sBh + off);
                ldsm_x4(bl[np*2][0], bl[np*2][1], bl[np*2+1][0], bl[np*2+1][1], sBl + off);
            }
            #pragma unroll
            for (int mi = 0; mi < 4; mi++) {
                uint32_t off = abase[mi] + ((uint32_t)(ks * 32 + acol_add) ^ asw[mi]);
                uint32_t ah[4], al[4];
                ldsm_x4(ah[0], ah[1], ah[2], ah[3], sAh + off);
                ldsm_x4(al[0], al[1], al[2], al[3], sAl + off);
                #pragma unroll
                for (int ni = 0; ni < 4; ni++) {
                    mma16816(acc[mi][ni], ah, bh[ni]);   // hi*hi
                    mma16816(acc[mi][ni], ah, bl[ni]);   // hi*lo
                    mma16816(acc[mi][ni], al, bh[ni]);   // lo*hi
                }
            }
        }
        __syncthreads();
    }

    // Epilogue
    const int colbase = blockIdx.y * 128 + wn * 32;
    #pragma unroll
    for (int mi = 0; mi < 4; mi++) {
        int r0 = m0 + wm * 64 + mi * 16 + g;
        #pragma unroll
        for (int ni = 0; ni < 4; ni++) {
            int c = colbase + ni * 8 + tig * 2;
            if (r0 < M)
                *(float2*)(C + (size_t)r0 * NT + c) = make_float2(acc[mi][ni][0], acc[mi][ni][1]);
            if (r0 + 8 < M)
                *(float2*)(C + (size_t)(r0 + 8) * NT + c) = make_float2(acc[mi][ni][2], acc[mi][ni][3]);
        }
    }
}

// ---------------------------------------------------------------------------
// Converters
// ---------------------------------------------------------------------------
__global__ void conv_feat(const float* __restrict__ F, __nv_bfloat16* __restrict__ hi,
                          __nv_bfloat16* __restrict__ lo, int n4) {
    int i = blockIdx.x * 256 + threadIdx.x;
    if (i >= n4) return;
    float4 v = ((const float4*)F)[i];
    float vv[4] = {v.x, v.y, v.z, v.w};
    __nv_bfloat16 hv[4], lv[4];
    #pragma unroll
    for (int j = 0; j < 4; j++) {
        hv[j] = __float2bfloat16(vv[j]);
        lv[j] = __float2bfloat16(vv[j] - __bfloat162float(hv[j]));
    }
    *(uint2*)(hi + (size_t)i * 4) = *(uint2*)hv;
    *(uint2*)(lo + (size_t)i * 4) = *(uint2*)lv;
}

__global__ void conv_w(const float* __restrict__ W, __nv_bfloat16* __restrict__ bh,
                       __nv_bfloat16* __restrict__ bl, int OUT, int Kk) {
    int i = blockIdx.x * 256 + threadIdx.x;
    if (i >= 2 * OUT * Kk) return;
    int j = i / Kk, k = i - j * Kk;
    float v = (j < OUT) ? W[(size_t)j * 2 * Kk + k]
                        : W[(size_t)(j - OUT) * 2 * Kk + Kk + k];
    __nv_bfloat16 h = __float2bfloat16(v);
    bh[i] = h;
    bl[i] = __float2bfloat16(v - __bfloat162float(h));
}

// ---------------------------------------------------------------------------
// Aggregation (layers 1-3): relu(S + mean(P)) -> bf16 hi/lo (row stride 128)
// ---------------------------------------------------------------------------
__global__ void agg_split(const float* __restrict__ SP, const int* __restrict__ neigh,
                          __nv_bfloat16* __restrict__ Hhi, __nv_bfloat16* __restrict__ Hlo,
                          int M) {
    const int w    = (blockIdx.x * blockDim.x + threadIdx.x) >> 5;
    const int lane = threadIdx.x & 31;
    if (w >= M) return;

    int nid = 0;
    if (lane < FANOUT) nid = neigh[(size_t)w * FANOUT + lane];

    float acc[4] = {};
    #pragma unroll
    for (int j = 0; j < FANOUT; j++) {
        int nj = __shfl_sync(0xffffffffu, nid, j);
        float4 v = *(const float4*)(SP + (size_t)nj * 256 + 128 + lane * 4);
        acc[0] += v.x; acc[1] += v.y; acc[2] += v.z; acc[3] += v.w;
    }
    float4 sv = *(const float4*)(SP + (size_t)w * 256 + lane * 4);
    const float inv = 1.0f / (float)FANOUT;
    float r[4];
    r[0] = fmaxf(fmaf(acc[0], inv, sv.x), 0.f);
    r[1] = fmaxf(fmaf(acc[1], inv, sv.y), 0.f);
    r[2] = fmaxf(fmaf(acc[2], inv, sv.z), 0.f);
    r[3] = fmaxf(fmaf(acc[3], inv, sv.w), 0.f);

    __nv_bfloat16 hv[4], lv[4];
    #pragma unroll
    for (int j = 0; j < 4; j++) {
        hv[j] = __float2bfloat16(r[j]);
        lv[j] = __float2bfloat16(r[j] - __bfloat162float(hv[j]));
    }
    *(uint2*)(Hhi + (size_t)w * 128 + lane * 4) = *(uint2*)hv;
    *(uint2*)(Hlo + (size_t)w * 128 + lane * 4) = *(uint2*)lv;
}

// Final aggregation (OUT=64): fp32 out, honors `nodes`
__global__ void agg_final(const float* __restrict__ SP, const int* __restrict__ neigh,
                          const int* __restrict__ nodes, float* __restrict__ out, int M) {
    const int w    = (blockIdx.x * blockDim.x + threadIdx.x) >> 5;
    const int lane = threadIdx.x & 31;
    if (w >= M) return;

    const int node = nodes[w];
    int nid = 0;
    if (lane < FANOUT) nid = neigh[(size_t)node * FANOUT + lane];

    float acc[2] = {};
    #pragma unroll
    for (int j = 0; j < FANOUT; j++) {
        int nj = __shfl_sync(0xffffffffu, nid, j);
        float2 v = *(const float2*)(SP + (size_t)nj * 128 + 64 + lane * 2);
        acc[0] += v.x; acc[1] += v.y;
    }
    float2 sv = *(const float2*)(SP + (size_t)node * 128 + lane * 2);
    const float inv = 1.0f / (float)FANOUT;
    float2 r;
    r.x = fmaxf(fmaf(acc[0], inv, sv.x), 0.f);
    r.y = fmaxf(fmaf(acc[1], inv, sv.y), 0.f);
    *(float2*)(out + (size_t)w * 64 + lane * 2) = r;
}

// ---------------------------------------------------------------------------

extern "C" void kernel_launch(void* const* d_in, const int* in_sizes, int n_in,
                              void* d_out, int out_size) {
    const float* features = (const float*)d_in[0];
    const float* W1       = (const float*)d_in[1];
    const float* W2       = (const float*)d_in[2];
    const float* W3       = (const float*)d_in[3];
    const float* W4       = (const float*)d_in[4];
    const int*   nodes    = (const int*)d_in[5];
    const int*   neigh    = (const int*)d_in[6];
    float*       out      = (float*)d_out;

    const int M = in_sizes[5];

    float* sp;
    __nv_bfloat16 *ahi, *alo, *bhi, *blo;
    cudaGetSymbolAddress((void**)&sp,  g_SP);
    cudaGetSymbolAddress((void**)&ahi, g_Ahi);
    cudaGetSymbolAddress((void**)&alo, g_Alo);
    cudaGetSymbolAddress((void**)&bhi, g_Bhi);
    cudaGetSymbolAddress((void**)&blo, g_Blo);

    constexpr int SMEM = 2 * 4 * 128 * 64 + 128;   // 2 stages x 4 tiles x 8KB + pad
    cudaFuncSetAttribute(gemm_mma<256, 256>, cudaFuncAttributeMaxDynamicSharedMemorySize, SMEM);
    cudaFuncSetAttribute(gemm_mma<128, 256>, cudaFuncAttributeMaxDynamicSharedMemorySize, SMEM);
    cudaFuncSetAttribute(gemm_mma<128, 128>, cudaFuncAttributeMaxDynamicSharedMemorySize, SMEM);

    // Weight packing (B layout [2*OUT, K], hi/lo)
    conv_w<<<(2 * 128 * 256 + 255) / 256, 256>>>(W1, bhi + WOFF1, blo + WOFF1, 128, 256);
    conv_w<<<(2 * 128 * 128 + 255) / 256, 256>>>(W2, bhi + WOFF2, blo + WOFF2, 128, 128);
    conv_w<<<(2 * 128 * 128 + 255) / 256, 256>>>(W3, bhi + WOFF3, blo + WOFF3, 128, 128);
    conv_w<<<(2 *  64 * 128 + 255) / 256, 256>>>(W4, bhi + WOFF4, blo + WOFF4,  64, 128);
    // Feature split
    conv_feat<<<(M * 64 + 255) / 256, 256>>>(features, ahi, alo, M * 64);

    const int gg = (M + 127) / 128;
    const int ab = (M + 7) / 8;

    // Layer 1
    gemm_mma<256, 256><<<dim3(gg, 2), 256, SMEM>>>(ahi, alo, bhi + WOFF1, blo + WOFF1, sp, M);
    agg_split<<<ab, 256>>>(sp, neigh, ahi, alo, M);
    // Layer 2
    gemm_mma<128, 256><<<dim3(gg, 2), 256, SMEM>>>(ahi, alo, bhi + WOFF2, blo + WOFF2, sp, M);
    agg_split<<<ab, 256>>>(sp, neigh, ahi, alo, M);
    // Layer 3
    gemm_mma<128, 256><<<dim3(gg, 2), 256, SMEM>>>(ahi, alo, bhi + WOFF3, blo + WOFF3, sp, M);
    agg_split<<<ab, 256>>>(sp, neigh, ahi, alo, M);
    // Layer 4
    gemm_mma<128, 128><<<dim3(gg, 1), 256, SMEM>>>(ahi, alo, bhi + WOFF4, blo + WOFF4, sp, M);
    agg_final<<<ab, 256>>>(sp, neigh, nodes, out, M);
}

// round 8
// speedup vs baseline: 3.2547x; 1.4782x over previous
#include <cuda_runtime.h>
#include <cuda_fp16.h>
#include <cstdint>
#include <cstddef>

#define N_NODES 100000
#define FANOUT  16

// Global scratch (all fp16 now)
__device__ __align__(16) __half g_SP[(size_t)N_NODES * 256];   // GEMM output [S|P]
__device__ __align__(16) __half g_Ah[(size_t)N_NODES * 256];   // activations (single fp16)
// Packed weights (B-operand layout [2*OUT, K]), fp16 hi/lo pair
#define WOFF1 0
#define WOFF2 65536
#define WOFF3 98304
#define WOFF4 131072
#define WTOT  147456
__device__ __align__(16) __half g_Bhi[WTOT];
__device__ __align__(16) __half g_Blo[WTOT];

// ---------------------------------------------------------------------------
// Helpers
// ---------------------------------------------------------------------------
__device__ __forceinline__ uint32_t smem_u32(const void* p) {
    return (uint32_t)__cvta_generic_to_shared(p);
}
__device__ __forceinline__ void cp16(uint32_t dst, const void* src, int sz) {
    asm volatile("cp.async.cg.shared.global [%0], [%1], 16, %2;\n"
                 :: "r"(dst), "l"(src), "r"(sz));
}
__device__ __forceinline__ void ldsm_x4(uint32_t& r0, uint32_t& r1, uint32_t& r2,
                                        uint32_t& r3, uint32_t addr) {
    asm volatile("ldmatrix.sync.aligned.m8n8.x4.shared.b16 {%0,%1,%2,%3}, [%4];"
                 : "=r"(r0), "=r"(r1), "=r"(r2), "=r"(r3) : "r"(addr));
}
__device__ __forceinline__ void mma16816(float c[4], const uint32_t a[4], const uint32_t b[2]) {
    asm volatile(
        "mma.sync.aligned.m16n8k16.row.col.f32.f16.f16.f32 "
        "{%0,%1,%2,%3}, {%4,%5,%6,%7}, {%8,%9}, {%0,%1,%2,%3};\n"
        : "+f"(c[0]), "+f"(c[1]), "+f"(c[2]), "+f"(c[3])
        : "r"(a[0]), "r"(a[1]), "r"(a[2]), "r"(a[3]), "r"(b[0]), "r"(b[1]));
}

// ---------------------------------------------------------------------------
// fp16 tensor GEMM, 2-MMA weight split: C = A @ (Bh + Bl)^T
// C[:, by*128 : by*128+128] fp16. BM=128, BN=128, BK=32, cp.async double-buffer.
// SMEM rows: 32 half = 64B, SW64 swizzle.
// ---------------------------------------------------------------------------
template<int K, int NT>
__global__ __launch_bounds__(256)
void gemm_mma(const __half* __restrict__ A,
              const __half* __restrict__ Bhi, const __half* __restrict__ Blo,
              __half* __restrict__ C, int M) {
    constexpr int NC    = K / 32;
    constexpr int TSZ   = 128 * 64;          // bytes per tile
    constexpr int STAGE = 3 * TSZ;           // A, Bh, Bl

    extern __shared__ char dsm[];
    const uint32_t base = (smem_u32(dsm) + 127u) & ~127u;

    const int tid  = threadIdx.x;
    const int wid  = tid >> 5;
    const int lane = tid & 31;
    const int g    = lane >> 2;
    const int tig  = lane & 3;
    const int wm   = wid & 1;
    const int wn   = wid >> 1;
    const int m0   = blockIdx.x * 128;

    const __half* Bh = Bhi + (size_t)blockIdx.y * 128 * K;
    const __half* Bl = Blo + (size_t)blockIdx.y * 128 * K;

    const int arow_add = ((lane >> 3) & 1) * 8;
    const int acol_add = ((lane >> 4) & 1) * 16;
    const int brow_add = ((lane >> 4) & 1) * 8;
    const int bcol_add = ((lane >> 3) & 1) * 16;

    uint32_t abase[4], asw[4];
    #pragma unroll
    for (int mi = 0; mi < 4; mi++) {
        int r = wm * 64 + mi * 16 + arow_add + (lane & 7);
        abase[mi] = r * 64;
        asw[mi]   = ((r >> 1) & 3) << 4;
    }
    uint32_t bbase[2], bsw[2];
    #pragma unroll
    for (int np = 0; np < 2; np++) {
        int r = wn * 32 + np * 16 + brow_add + (lane & 7);
        bbase[np] = r * 64;
        bsw[np]   = ((r >> 1) & 3) << 4;
    }

    auto load_chunk = [&](int kc, int s) {
        const uint32_t sb = base + s * STAGE;
        #pragma unroll
        for (int u = tid; u < 512; u += 256) {
            int row = u >> 2, c16 = u & 3;
            uint32_t off = row * 64 + ((c16 ^ ((row >> 1) & 3)) << 4);
            int gr = m0 + row;
            int szA = (gr < M) ? 16 : 0;
            size_t giA = (size_t)gr * K + kc * 32 + c16 * 8;
            size_t giB = (size_t)row * K + kc * 32 + c16 * 8;
            cp16(sb + off,           A  + giA, szA);
            cp16(sb + TSZ + off,     Bh + giB, 16);
            cp16(sb + 2 * TSZ + off, Bl + giB, 16);
        }
        asm volatile("cp.async.commit_group;" ::: "memory");
    };

    float acc[4][4][4] = {};

    load_chunk(0, 0);

    for (int kc = 0; kc < NC; kc++) {
        const int s = kc & 1;
        if (kc + 1 < NC) {
            load_chunk(kc + 1, s ^ 1);
            asm volatile("cp.async.wait_group 1;" ::: "memory");
        } else {
            asm volatile("cp.async.wait_group 0;" ::: "memory");
        }
        __syncthreads();

        const uint32_t sA  = base + s * STAGE;
        const uint32_t sBh = sA + TSZ;
        const uint32_t sBl = sA + 2 * TSZ;

        #pragma unroll
        for (int ks = 0; ks < 2; ks++) {
            uint32_t bh[4][2], bl[4][2];
            #pragma unroll
            for (int np = 0; np < 2; np++) {
                uint32_t off = bbase[np] + ((uint32_t)(ks * 32 + bcol_add) ^ bsw[np]);
                ldsm_x4(bh[np*2][0], bh[np*2][1], bh[np*2+1][0], bh[np*2+1][1], sBh + off);
                ldsm_x4(bl[np*2][0], bl[np*2][1], bl[np*2+1][0], bl[np*2+1][1], sBl + off);
            }
            #pragma unroll
            for (int mi = 0; mi < 4; mi++) {
                uint32_t off = abase[mi] + ((uint32_t)(ks * 32 + acol_add) ^ asw[mi]);
                uint32_t ah[4];
                ldsm_x4(ah[0], ah[1], ah[2], ah[3], sA + off);
                #pragma unroll
                for (int ni = 0; ni < 4; ni++) {
                    mma16816(acc[mi][ni], ah, bh[ni]);   // A * Bhi
                    mma16816(acc[mi][ni], ah, bl[ni]);   // A * Blo
                }
            }
        }
        __syncthreads();
    }

    // Epilogue: fp16 output
    const int colbase = blockIdx.y * 128 + wn * 32;
    #pragma unroll
    for (int mi = 0; mi < 4; mi++) {
        int r0 = m0 + wm * 64 + mi * 16 + g;
        #pragma unroll
        for (int ni = 0; ni < 4; ni++) {
            int c = colbase + ni * 8 + tig * 2;
            if (r0 < M)
                *(__half2*)(C + (size_t)r0 * NT + c) =
                    __floats2half2_rn(acc[mi][ni][0], acc[mi][ni][1]);
            if (r0 + 8 < M)
                *(__half2*)(C + (size_t)(r0 + 8) * NT + c) =
                    __floats2half2_rn(acc[mi][ni][2], acc[mi][ni][3]);
        }
    }
}

// ---------------------------------------------------------------------------
// Converters
// ---------------------------------------------------------------------------
__global__ void conv_feat(const float* __restrict__ F, __half* __restrict__ Ah, int n4) {
    int i = blockIdx.x * 256 + threadIdx.x;
    if (i >= n4) return;
    float4 v = ((const float4*)F)[i];
    __half2 h0 = __floats2half2_rn(v.x, v.y);
    __half2 h1 = __floats2half2_rn(v.z, v.w);
    *(uint2*)(Ah + (size_t)i * 4) = make_uint2(*(uint32_t*)&h0, *(uint32_t*)&h1);
}

__global__ void conv_w_all(const float* __restrict__ W1, const float* __restrict__ W2,
                           const float* __restrict__ W3, const float* __restrict__ W4,
                           __half* __restrict__ bh, __half* __restrict__ bl) {
    int i = blockIdx.x * 256 + threadIdx.x;
    if (i >= WTOT) return;
    const float* W; int OUT, Kk, off;
    if (i < WOFF2)      { W = W1; OUT = 128; Kk = 256; off = WOFF1; }
    else if (i < WOFF3) { W = W2; OUT = 128; Kk = 128; off = WOFF2; }
    else if (i < WOFF4) { W = W3; OUT = 128; Kk = 128; off = WOFF3; }
    else                { W = W4; OUT = 64;  Kk = 128; off = WOFF4; }
    int t = i - off;
    int j = t / Kk, k = t - j * Kk;
    float v = (j < OUT) ? W[(size_t)j * 2 * Kk + k]
                        : W[(size_t)(j - OUT) * 2 * Kk + Kk + k];
    __half h = __float2half_rn(v);
    bh[i] = h;
    bl[i] = __float2half_rn(v - __half2float(h));
}

// ---------------------------------------------------------------------------
// Aggregation (layers 1-3): relu(S + mean(P)) -> single fp16 h (row stride 128)
// SP fp16 [M, 256], S = cols [0,128), P = cols [128,256).
// ---------------------------------------------------------------------------
__global__ void agg_split(const __half* __restrict__ SP, const int* __restrict__ neigh,
                          __half* __restrict__ H, int M) {
    const int w    = (blockIdx.x * blockDim.x + threadIdx.x) >> 5;
    const int lane = threadIdx.x & 31;
    if (w >= M) return;

    int nid = 0;
    if (lane < FANOUT) nid = neigh[(size_t)w * FANOUT + lane];

    float acc[4] = {};
    #pragma unroll
    for (int j = 0; j < FANOUT; j++) {
        int nj = __shfl_sync(0xffffffffu, nid, j);
        uint2 raw = *(const uint2*)(SP + (size_t)nj * 256 + 128 + lane * 4);
        float2 f0 = __half22float2(*(__half2*)&raw.x);
        float2 f1 = __half22float2(*(__half2*)&raw.y);
        acc[0] += f0.x; acc[1] += f0.y; acc[2] += f1.x; acc[3] += f1.y;
    }
    uint2 sraw = *(const uint2*)(SP + (size_t)w * 256 + lane * 4);
    float2 s0 = __half22float2(*(__half2*)&sraw.x);
    float2 s1 = __half22float2(*(__half2*)&sraw.y);

    const float inv = 1.0f / (float)FANOUT;
    float r0 = fmaxf(fmaf(acc[0], inv, s0.x), 0.f);
    float r1 = fmaxf(fmaf(acc[1], inv, s0.y), 0.f);
    float r2 = fmaxf(fmaf(acc[2], inv, s1.x), 0.f);
    float r3 = fmaxf(fmaf(acc[3], inv, s1.y), 0.f);

    __half2 o0 = __floats2half2_rn(r0, r1);
    __half2 o1 = __floats2half2_rn(r2, r3);
    *(uint2*)(H + (size_t)w * 128 + lane * 4) = make_uint2(*(uint32_t*)&o0, *(uint32_t*)&o1);
}

// Final aggregation (OUT=64): SP fp16 [M,128], fp32 out, honors `nodes`
__global__ void agg_final(const __half* __restrict__ SP, const int* __restrict__ neigh,
                          const int* __restrict__ nodes, float* __restrict__ out, int M) {
    const int w    = (blockIdx.x * blockDim.x + threadIdx.x) >> 5;
    const int lane = threadIdx.x & 31;
    if (w >= M) return;

    const int node = nodes[w];
    int nid = 0;
    if (lane < FANOUT) nid = neigh[(size_t)node * FANOUT + lane];

    float acc[2] = {};
    #pragma unroll
    for (int j = 0; j < FANOUT; j++) {
        int nj = __shfl_sync(0xffffffffu, nid, j);
        uint32_t raw = *(const uint32_t*)(SP + (size_t)nj * 128 + 64 + lane * 2);
        float2 f = __half22float2(*(__half2*)&raw);
        acc[0] += f.x; acc[1] += f.y;
    }
    uint32_t sraw = *(const uint32_t*)(SP + (size_t)node * 128 + lane * 2);
    float2 sv = __half22float2(*(__half2*)&sraw);

    const float inv = 1.0f / (float)FANOUT;
    float2 r;
    r.x = fmaxf(fmaf(acc[0], inv, sv.x), 0.f);
    r.y = fmaxf(fmaf(acc[1], inv, sv.y), 0.f);
    *(float2*)(out + (size_t)w * 64 + lane * 2) = r;
}

// ---------------------------------------------------------------------------

extern "C" void kernel_launch(void* const* d_in, const int* in_sizes, int n_in,
                              void* d_out, int out_size) {
    const float* features = (const float*)d_in[0];
    const float* W1       = (const float*)d_in[1];
    const float* W2       = (const float*)d_in[2];
    const float* W3       = (const float*)d_in[3];
    const float* W4       = (const float*)d_in[4];
    const int*   nodes    = (const int*)d_in[5];
    const int*   neigh    = (const int*)d_in[6];
    float*       out      = (float*)d_out;

    const int M = in_sizes[5];

    __half *sp, *ah, *bhi, *blo;
    cudaGetSymbolAddress((void**)&sp,  g_SP);
    cudaGetSymbolAddress((void**)&ah,  g_Ah);
    cudaGetSymbolAddress((void**)&bhi, g_Bhi);
    cudaGetSymbolAddress((void**)&blo, g_Blo);

    constexpr int SMEM = 2 * 3 * 128 * 64 + 128;   // 2 stages x 3 tiles x 8KB + pad
    cudaFuncSetAttribute(gemm_mma<256, 256>, cudaFuncAttributeMaxDynamicSharedMemorySize, SMEM);
    cudaFuncSetAttribute(gemm_mma<128, 256>, cudaFuncAttributeMaxDynamicSharedMemorySize, SMEM);
    cudaFuncSetAttribute(gemm_mma<128, 128>, cudaFuncAttributeMaxDynamicSharedMemorySize, SMEM);

    // Weight packing (one launch) + feature conversion
    conv_w_all<<<(WTOT + 255) / 256, 256>>>(W1, W2, W3, W4, bhi, blo);
    conv_feat<<<(M * 64 + 255) / 256, 256>>>(features, ah, M * 64);

    const int gg = (M + 127) / 128;
    const int ab = (M + 7) / 8;

    // Layer 1
    gemm_mma<256, 256><<<dim3(gg, 2), 256, SMEM>>>(ah, bhi + WOFF1, blo + WOFF1, sp, M);
    agg_split<<<ab, 256>>>(sp, neigh, ah, M);
    // Layer 2
    gemm_mma<128, 256><<<dim3(gg, 2), 256, SMEM>>>(ah, bhi + WOFF2, blo + WOFF2, sp, M);
    agg_split<<<ab, 256>>>(sp, neigh, ah, M);
    // Layer 3
    gemm_mma<128, 256><<<dim3(gg, 2), 256, SMEM>>>(ah, bhi + WOFF3, blo + WOFF3, sp, M);
    agg_split<<<ab, 256>>>(sp, neigh, ah, M);
    // Layer 4
    gemm_mma<128, 128><<<dim3(gg, 1), 256, SMEM>>>(ah, bhi + WOFF4, blo + WOFF4, sp, M);
    agg_final<<<ab, 256>>>(sp, neigh, nodes, out, M);
}

// round 10
// speedup vs baseline: 3.5843x; 1.1012x over previous
#include <cuda_runtime.h>
#include <cuda_fp16.h>
#include <cstdint>
#include <cstddef>

#define N_NODES 100000
#define FANOUT  16

// Global scratch (fp16)
__device__ __align__(16) __half g_SP[(size_t)N_NODES * 256];
__device__ __align__(16) __half g_Ah[(size_t)N_NODES * 256];
__device__ __align__(16) __half g_Hm[(size_t)N_NODES * 128];
// Packed weights, fp16 hi/lo pair
#define WOFF1 0
#define WOFF2 65536
#define WOFF3 98304
#define WOFF4 131072
#define WTOT  147456
__device__ __align__(16) __half g_Bhi[WTOT];
__device__ __align__(16) __half g_Blo[WTOT];

// ---------------------------------------------------------------------------
// Helpers
// ---------------------------------------------------------------------------
__device__ __forceinline__ uint32_t smem_u32(const void* p) {
    return (uint32_t)__cvta_generic_to_shared(p);
}
__device__ __forceinline__ void cp16(uint32_t dst, const void* src, int sz) {
    asm volatile("cp.async.cg.shared.global [%0], [%1], 16, %2;\n"
                 :: "r"(dst), "l"(src), "r"(sz));
}
__device__ __forceinline__ void ldsm_x4(uint32_t& r0, uint32_t& r1, uint32_t& r2,
                                        uint32_t& r3, uint32_t addr) {
    asm volatile("ldmatrix.sync.aligned.m8n8.x4.shared.b16 {%0,%1,%2,%3}, [%4];"
                 : "=r"(r0), "=r"(r1), "=r"(r2), "=r"(r3) : "r"(addr));
}
__device__ __forceinline__ void mma16816(float c[4], const uint32_t a[4], const uint32_t b[2]) {
    asm volatile(
        "mma.sync.aligned.m16n8k16.row.col.f32.f16.f16.f32 "
        "{%0,%1,%2,%3}, {%4,%5,%6,%7}, {%8,%9}, {%0,%1,%2,%3};\n"
        : "+f"(c[0]), "+f"(c[1]), "+f"(c[2]), "+f"(c[3])
        : "r"(a[0]), "r"(a[1]), "r"(a[2]), "r"(a[3]), "r"(b[0]), "r"(b[1]));
}

// ---------------------------------------------------------------------------
// fp16 tensor GEMM, 2-MMA weight split: C = act( A @ (Bh + Bl)^T )
// SPLITA: A k-cols [0,K/2) from A, [K/2,K) from A2 (both row stride 128).
// BM=128, BN=128, BK=32; 4-stage cp.async pipeline; SW64-swizzled smem.
// ---------------------------------------------------------------------------
template<int K, int NT, bool RELU, bool SPLITA>
__global__ __launch_bounds__(256, 2)
void gemm_mma(const __half* __restrict__ A, const __half* __restrict__ A2,
              const __half* __restrict__ Bhi, const __half* __restrict__ Blo,
              __half* __restrict__ C, int M) {
    constexpr int NC    = K / 32;
    constexpr int TSZ   = 128 * 64;          // bytes per tile
    constexpr int STAGE = 3 * TSZ;           // A, Bh, Bl
    constexpr int AST   = SPLITA ? 128 : K;  // A row stride (elements)

    extern __shared__ char dsm[];
    const uint32_t base = (smem_u32(dsm) + 127u) & ~127u;

    const int tid  = threadIdx.x;
    const int wid  = tid >> 5;
    const int lane = tid & 31;
    const int g    = lane >> 2;
    const int tig  = lane & 3;
    const int wm   = wid & 1;
    const int wn   = wid >> 1;
    const int m0   = blockIdx.x * 128;

    const __half* Bh = Bhi + (size_t)blockIdx.y * 128 * K;
    const __half* Bl = Blo + (size_t)blockIdx.y * 128 * K;

    const int arow_add = ((lane >> 3) & 1) * 8;
    const int acol_add = ((lane >> 4) & 1) * 16;
    const int brow_add = ((lane >> 4) & 1) * 8;
    const int bcol_add = ((lane >> 3) & 1) * 16;

    uint32_t abase[4], asw[4];
    #pragma unroll
    for (int mi = 0; mi < 4; mi++) {
        int r = wm * 64 + mi * 16 + arow_add + (lane & 7);
        abase[mi] = r * 64;
        asw[mi]   = ((r >> 1) & 3) << 4;
    }
    uint32_t bbase[2], bsw[2];
    #pragma unroll
    for (int np = 0; np < 2; np++) {
        int r = wn * 32 + np * 16 + brow_add + (lane & 7);
        bbase[np] = r * 64;
        bsw[np]   = ((r >> 1) & 3) << 4;
    }

    auto load_chunk = [&](int kc, int s) {
        const uint32_t sb = base + s * STAGE;
        const __half* Asrc = (SPLITA && kc >= NC / 2) ? A2 : A;
        const int acol = SPLITA ? ((kc & (NC / 2 - 1)) * 32) : kc * 32;
        #pragma unroll
        for (int u = tid; u < 512; u += 256) {
            int row = u >> 2, c16 = u & 3;
            uint32_t off = row * 64 + ((c16 ^ ((row >> 1) & 3)) << 4);
            int gr = m0 + row;
            int szA = (gr < M) ? 16 : 0;
            size_t giA = (size_t)gr * AST + acol + c16 * 8;
            size_t giB = (size_t)row * K + kc * 32 + c16 * 8;
            cp16(sb + off,           Asrc + giA, szA);
            cp16(sb + TSZ + off,     Bh + giB, 16);
            cp16(sb + 2 * TSZ + off, Bl + giB, 16);
        }
        asm volatile("cp.async.commit_group;" ::: "memory");
    };

    float acc[4][4][4] = {};

    load_chunk(0, 0);
    load_chunk(1, 1);
    load_chunk(2, 2);

    #pragma unroll
    for (int kc = 0; kc < NC; kc++) {
        const int s = kc & 3;
        if (kc + 3 <= NC)      asm volatile("cp.async.wait_group 2;" ::: "memory");
        else if (kc + 2 <= NC) asm volatile("cp.async.wait_group 1;" ::: "memory");
        else                   asm volatile("cp.async.wait_group 0;" ::: "memory");
        __syncthreads();
        if (kc + 3 < NC) load_chunk(kc + 3, (kc + 3) & 3);

        const uint32_t sA  = base + s * STAGE;
        const uint32_t sBh = sA + TSZ;
        const uint32_t sBl = sA + 2 * TSZ;

        #pragma unroll
        for (int ks = 0; ks < 2; ks++) {
            uint32_t bh[4][2], bl[4][2];
            #pragma unroll
            for (int np = 0; np < 2; np++) {
                uint32_t off = bbase[np] + ((uint32_t)(ks * 32 + bcol_add) ^ bsw[np]);
                ldsm_x4(bh[np*2][0], bh[np*2][1], bh[np*2+1][0], bh[np*2+1][1], sBh + off);
                ldsm_x4(bl[np*2][0], bl[np*2][1], bl[np*2+1][0], bl[np*2+1][1], sBl + off);
            }
            #pragma unroll
            for (int mi = 0; mi < 4; mi++) {
                uint32_t off = abase[mi] + ((uint32_t)(ks * 32 + acol_add) ^ asw[mi]);
                uint32_t ah[4];
                ldsm_x4(ah[0], ah[1], ah[2], ah[3], sA + off);
                #pragma unroll
                for (int ni = 0; ni < 4; ni++) {
                    mma16816(acc[mi][ni], ah, bh[ni]);
                    mma16816(acc[mi][ni], ah, bl[ni]);
                }
            }
        }
    }
    __syncthreads();

    // Epilogue
    const int colbase = blockIdx.y * 128 + wn * 32;
    #pragma unroll
    for (int mi = 0; mi < 4; mi++) {
        int r0 = m0 + wm * 64 + mi * 16 + g;
        #pragma unroll
        for (int ni = 0; ni < 4; ni++) {
            int c = colbase + ni * 8 + tig * 2;
            float v0 = acc[mi][ni][0], v1 = acc[mi][ni][1];
            float v2 = acc[mi][ni][2], v3 = acc[mi][ni][3];
            if (RELU) {
                v0 = fmaxf(v0, 0.f); v1 = fmaxf(v1, 0.f);
                v2 = fmaxf(v2, 0.f); v3 = fmaxf(v3, 0.f);
            }
            if (r0 < M)
                *(__half2*)(C + (size_t)r0 * NT + c) = __floats2half2_rn(v0, v1);
            if (r0 + 8 < M)
                *(__half2*)(C + (size_t)(r0 + 8) * NT + c) = __floats2half2_rn(v2, v3);
        }
    }
}

// ---------------------------------------------------------------------------
// Converters
// ---------------------------------------------------------------------------
__global__ void conv_feat(const float* __restrict__ F, __half* __restrict__ Ah, int n4) {
    int i = blockIdx.x * 256 + threadIdx.x;
    if (i >= n4) return;
    float4 v = ((const float4*)F)[i];
    __half2 h0 = __floats2half2_rn(v.x, v.y);
    __half2 h1 = __floats2half2_rn(v.z, v.w);
    *(uint2*)(Ah + (size_t)i * 4) = make_uint2(*(uint32_t*)&h0, *(uint32_t*)&h1);
}

__global__ void conv_w_all(const float* __restrict__ W1, const float* __restrict__ W2,
                           const float* __restrict__ W3, const float* __restrict__ W4,
                           __half* __restrict__ bh, __half* __restrict__ bl) {
    int i = blockIdx.x * 256 + threadIdx.x;
    if (i >= WTOT) return;
    float v;
    if (i < WOFF2) {                 // L1: stacked [Ws1; Wn1], K=256
        int t = i, j = t >> 8, k = t & 255;
        v = (j < 128) ? W1[(size_t)j * 512 + k] : W1[(size_t)(j - 128) * 512 + 256 + k];
    } else if (i < WOFF3) {          // L2: identity [128, 256]
        v = W2[i - WOFF2];
    } else if (i < WOFF4) {          // L3: identity
        v = W3[i - WOFF3];
    } else {                         // L4: stacked [Ws4; Wn4], K=128
        int t = i - WOFF4, j = t >> 7, k = t & 127;
        v = (j < 64) ? W4[(size_t)j * 256 + k] : W4[(size_t)(j - 64) * 256 + 128 + k];
    }
    __half h = __float2half_rn(v);
    bh[i] = h;
    bl[i] = __float2half_rn(v - __half2float(h));
}

// ---------------------------------------------------------------------------
// mean_h: Hm[w,:] = (1/16) * sum_j H[neigh[w][j], :]   (128 cols fp16)
// ---------------------------------------------------------------------------
__global__ void mean_h(const __half* __restrict__ H, const int* __restrict__ neigh,
                       __half* __restrict__ Hm, int M) {
    const int w    = (blockIdx.x * blockDim.x + threadIdx.x) >> 5;
    const int lane = threadIdx.x & 31;
    if (w >= M) return;

    int nid = 0;
    if (lane < FANOUT) nid = neigh[(size_t)w * FANOUT + lane];

    float acc[4] = {};
    #pragma unroll
    for (int j = 0; j < FANOUT; j++) {
        int nj = __shfl_sync(0xffffffffu, nid, j);
        uint2 raw = *(const uint2*)(H + (size_t)nj * 128 + lane * 4);
        float2 f0 = __half22float2(*(__half2*)&raw.x);
        float2 f1 = __half22float2(*(__half2*)&raw.y);
        acc[0] += f0.x; acc[1] += f0.y; acc[2] += f1.x; acc[3] += f1.y;
    }
    const float inv = 1.0f / (float)FANOUT;
    __half2 o0 = __floats2half2_rn(acc[0] * inv, acc[1] * inv);
    __half2 o1 = __floats2half2_rn(acc[2] * inv, acc[3] * inv);
    *(uint2*)(Hm + (size_t)w * 128 + lane * 4) = make_uint2(*(uint32_t*)&o0, *(uint32_t*)&o1);
}

// ---------------------------------------------------------------------------
// agg_split (L1): relu(S + mean(P)) -> fp16 h (row stride 128); SP [M,256]
// ---------------------------------------------------------------------------
__global__ void agg_split(const __half* __restrict__ SP, const int* __restrict__ neigh,
                          __half* __restrict__ H, int M) {
    const int w    = (blockIdx.x * blockDim.x + threadIdx.x) >> 5;
    const int lane = threadIdx.x & 31;
    if (w >= M) return;

    int nid = 0;
    if (lane < FANOUT) nid = neigh[(size_t)w * FANOUT + lane];

    float acc[4] = {};
    #pragma unroll
    for (int j = 0; j < FANOUT; j++) {
        int nj = __shfl_sync(0xffffffffu, nid, j);
        uint2 raw = *(const uint2*)(SP + (size_t)nj * 256 + 128 + lane * 4);
        float2 f0 = __half22float2(*(__half2*)&raw.x);
        float2 f1 = __half22float2(*(__half2*)&raw.y);
        acc[0] += f0.x; acc[1] += f0.y; acc[2] += f1.x; acc[3] += f1.y;
    }
    uint2 sraw = *(const uint2*)(SP + (size_t)w * 256 + lane * 4);
    float2 s0 = __half22float2(*(__half2*)&sraw.x);
    float2 s1 = __half22float2(*(__half2*)&sraw.y);

    const float inv = 1.0f / (float)FANOUT;
    float r0 = fmaxf(fmaf(acc[0], inv, s0.x), 0.f);
    float r1 = fmaxf(fmaf(acc[1], inv, s0.y), 0.f);
    float r2 = fmaxf(fmaf(acc[2], inv, s1.x), 0.f);
    float r3 = fmaxf(fmaf(acc[3], inv, s1.y), 0.f);

    __half2 o0 = __floats2half2_rn(r0, r1);
    __half2 o1 = __floats2half2_rn(r2, r3);
    *(uint2*)(H + (size_t)w * 128 + lane * 4) = make_uint2(*(uint32_t*)&o0, *(uint32_t*)&o1);
}

// Final aggregation (L4): SP fp16 [M,128] (S=cols 0-63, P=64-127), fp32 out via nodes
__global__ void agg_final(const __half* __restrict__ SP, const int* __restrict__ neigh,
                          const int* __restrict__ nodes, float* __restrict__ out, int M) {
    const int w    = (blockIdx.x * blockDim.x + threadIdx.x) >> 5;
    const int lane = threadIdx.x & 31;
    if (w >= M) return;

    const int node = nodes[w];
    int nid = 0;
    if (lane < FANOUT) nid = neigh[(size_t)node * FANOUT + lane];

    float acc[2] = {};
    #pragma unroll
    for (int j = 0; j < FANOUT; j++) {
        int nj = __shfl_sync(0xffffffffu, nid, j);
        uint32_t raw = *(const uint32_t*)(SP + (size_t)nj * 128 + 64 + lane * 2);
        float2 f = __half22float2(*(__half2*)&raw);
        acc[0] += f.x; acc[1] += f.y;
    }
    uint32_t sraw = *(const uint32_t*)(SP + (size_t)node * 128 + lane * 2);
    float2 sv = __half22float2(*(__half2*)&sraw);

    const float inv = 1.0f / (float)FANOUT;
    float2 r;
    r.x = fmaxf(fmaf(acc[0], inv, sv.x), 0.f);
    r.y = fmaxf(fmaf(acc[1], inv, sv.y), 0.f);
    *(float2*)(out + (size_t)w * 64 + lane * 2) = r;
}

// ---------------------------------------------------------------------------

extern "C" void kernel_launch(void* const* d_in, const int* in_sizes, int n_in,
                              void* d_out, int out_size) {
    const float* features = (const float*)d_in[0];
    const float* W1       = (const float*)d_in[1];
    const float* W2       = (const float*)d_in[2];
    const float* W3       = (const float*)d_in[3];
    const float* W4       = (const float*)d_in[4];
    const int*   nodes    = (const int*)d_in[5];
    const int*   neigh    = (const int*)d_in[6];
    float*       out      = (float*)d_out;

    const int M = in_sizes[5];

    __half *sp, *ah, *hm, *bhi, *blo;
    cudaGetSymbolAddress((void**)&sp,  g_SP);
    cudaGetSymbolAddress((void**)&ah,  g_Ah);
    cudaGetSymbolAddress((void**)&hm,  g_Hm);
    cudaGetSymbolAddress((void**)&bhi, g_Bhi);
    cudaGetSymbolAddress((void**)&blo, g_Blo);

    constexpr int SMEM = 4 * 3 * 128 * 64 + 128;   // 4 stages x 3 tiles x 8KB + pad
    cudaFuncSetAttribute(gemm_mma<256, 256, false, false>,
                         cudaFuncAttributeMaxDynamicSharedMemorySize, SMEM);
    cudaFuncSetAttribute(gemm_mma<256, 128, true, true>,
                         cudaFuncAttributeMaxDynamicSharedMemorySize, SMEM);
    cudaFuncSetAttribute(gemm_mma<128, 128, false, false>,
                         cudaFuncAttributeMaxDynamicSharedMemorySize, SMEM);

    conv_w_all<<<(WTOT + 255) / 256, 256>>>(W1, W2, W3, W4, bhi, blo);
    conv_feat<<<(M * 64 + 255) / 256, 256>>>(features, ah, M * 64);

    const int gg = (M + 127) / 128;
    const int ab = (M + 7) / 8;

    // Layer 1: project-first (SP = [S|P]), then combine+relu
    gemm_mma<256, 256, false, false><<<dim3(gg, 2), 256, SMEM>>>(
        ah, nullptr, bhi + WOFF1, blo + WOFF1, sp, M);
    agg_split<<<ab, 256>>>(sp, neigh, ah, M);            // h1 -> g_Ah (stride 128)

    // Layer 2: gather-first, relu fused in GEMM
    mean_h<<<ab, 256>>>(ah, neigh, hm, M);
    gemm_mma<256, 128, true, true><<<dim3(gg, 1), 256, SMEM>>>(
        ah, hm, bhi + WOFF2, blo + WOFF2, sp, M);        // h2 -> g_SP (stride 128)

    // Layer 3
    mean_h<<<ab, 256>>>(sp, neigh, hm, M);
    gemm_mma<256, 128, true, true><<<dim3(gg, 1), 256, SMEM>>>(
        sp, hm, bhi + WOFF3, blo + WOFF3, ah, M);        // h3 -> g_Ah

    // Layer 4: project-first (SP4 = [S|P], 128 cols), then combine+relu via nodes
    gemm_mma<128, 128, false, false><<<dim3(gg, 1), 256, SMEM>>>(
        ah, nullptr, bhi + WOFF4, blo + WOFF4, sp, M);
    agg_final<<<ab, 256>>>(sp, neigh, nodes, out, M);
}

// round 11
// speedup vs baseline: 4.3151x; 1.2039x over previous
#include <cuda_runtime.h>
#include <cuda_fp16.h>
#include <cstdint>
#include <cstddef>

#define N_NODES 100000
#define FANOUT  16

// Global scratch (fp16)
__device__ __align__(16) __half g_SP[(size_t)N_NODES * 256];
__device__ __align__(16) __half g_Ah[(size_t)N_NODES * 256];
__device__ __align__(16) __half g_Hm[(size_t)N_NODES * 128];
// Packed weights (B layout), single fp16
#define WOFF1 0
#define WOFF2 65536
#define WOFF3 98304
#define WOFF4 131072
#define WTOT  147456
__device__ __align__(16) __half g_Bw[WTOT];

// ---------------------------------------------------------------------------
// Helpers
// ---------------------------------------------------------------------------
__device__ __forceinline__ uint32_t smem_u32(const void* p) {
    return (uint32_t)__cvta_generic_to_shared(p);
}
__device__ __forceinline__ void cp16(uint32_t dst, const void* src, int sz) {
    asm volatile("cp.async.cg.shared.global [%0], [%1], 16, %2;\n"
                 :: "r"(dst), "l"(src), "r"(sz));
}
__device__ __forceinline__ void ldsm_x4(uint32_t& r0, uint32_t& r1, uint32_t& r2,
                                        uint32_t& r3, uint32_t addr) {
    asm volatile("ldmatrix.sync.aligned.m8n8.x4.shared.b16 {%0,%1,%2,%3}, [%4];"
                 : "=r"(r0), "=r"(r1), "=r"(r2), "=r"(r3) : "r"(addr));
}
__device__ __forceinline__ void mma16816(float c[4], const uint32_t a[4], const uint32_t b[2]) {
    asm volatile(
        "mma.sync.aligned.m16n8k16.row.col.f32.f16.f16.f32 "
        "{%0,%1,%2,%3}, {%4,%5,%6,%7}, {%8,%9}, {%0,%1,%2,%3};\n"
        : "+f"(c[0]), "+f"(c[1]), "+f"(c[2]), "+f"(c[3])
        : "r"(a[0]), "r"(a[1]), "r"(a[2]), "r"(a[3]), "r"(b[0]), "r"(b[1]));
}

// ---------------------------------------------------------------------------
// fp16 tensor GEMM: C = act( A @ B^T )
// SPLITA: A k-cols [0,K/2) from A, [K/2,K) from A2 (both row stride 128).
// BM=128, BN=128, BK=32; 4-stage cp.async pipeline; SW64-swizzled smem.
// ---------------------------------------------------------------------------
template<int K, int NT, bool RELU, bool SPLITA>
__global__ __launch_bounds__(256, 2)
void gemm_mma(const __half* __restrict__ A, const __half* __restrict__ A2,
              const __half* __restrict__ B, __half* __restrict__ C, int M) {
    constexpr int NC    = K / 32;
    constexpr int TSZ   = 128 * 64;          // bytes per tile
    constexpr int STAGE = 2 * TSZ;           // A, B
    constexpr int AST   = SPLITA ? 128 : K;  // A row stride (elements)

    extern __shared__ char dsm[];
    const uint32_t base = (smem_u32(dsm) + 127u) & ~127u;

    const int tid  = threadIdx.x;
    const int wid  = tid >> 5;
    const int lane = tid & 31;
    const int g    = lane >> 2;
    const int tig  = lane & 3;
    const int wm   = wid & 1;
    const int wn   = wid >> 1;
    const int m0   = blockIdx.x * 128;

    const __half* Bp = B + (size_t)blockIdx.y * 128 * K;

    const int arow_add = ((lane >> 3) & 1) * 8;
    const int acol_add = ((lane >> 4) & 1) * 16;
    const int brow_add = ((lane >> 4) & 1) * 8;
    const int bcol_add = ((lane >> 3) & 1) * 16;

    uint32_t abase[4], asw[4];
    #pragma unroll
    for (int mi = 0; mi < 4; mi++) {
        int r = wm * 64 + mi * 16 + arow_add + (lane & 7);
        abase[mi] = r * 64;
        asw[mi]   = ((r >> 1) & 3) << 4;
    }
    uint32_t bbase[2], bsw[2];
    #pragma unroll
    for (int np = 0; np < 2; np++) {
        int r = wn * 32 + np * 16 + brow_add + (lane & 7);
        bbase[np] = r * 64;
        bsw[np]   = ((r >> 1) & 3) << 4;
    }

    auto load_chunk = [&](int kc, int s) {
        const uint32_t sb = base + s * STAGE;
        const __half* Asrc = (SPLITA && kc >= NC / 2) ? A2 : A;
        const int acol = SPLITA ? ((kc & (NC / 2 - 1)) * 32) : kc * 32;
        #pragma unroll
        for (int u = tid; u < 512; u += 256) {
            int row = u >> 2, c16 = u & 3;
            uint32_t off = row * 64 + ((c16 ^ ((row >> 1) & 3)) << 4);
            int gr = m0 + row;
            int szA = (gr < M) ? 16 : 0;
            size_t giA = (size_t)gr * AST + acol + c16 * 8;
            size_t giB = (size_t)row * K + kc * 32 + c16 * 8;
            cp16(sb + off,       Asrc + giA, szA);
            cp16(sb + TSZ + off, Bp + giB, 16);
        }
        asm volatile("cp.async.commit_group;" ::: "memory");
    };

    float acc[4][4][4] = {};

    load_chunk(0, 0);
    load_chunk(1, 1);
    load_chunk(2, 2);

    #pragma unroll
    for (int kc = 0; kc < NC; kc++) {
        const int s = kc & 3;
        if (kc + 3 <= NC)      asm volatile("cp.async.wait_group 2;" ::: "memory");
        else if (kc + 2 <= NC) asm volatile("cp.async.wait_group 1;" ::: "memory");
        else                   asm volatile("cp.async.wait_group 0;" ::: "memory");
        __syncthreads();
        if (kc + 3 < NC) load_chunk(kc + 3, (kc + 3) & 3);

        const uint32_t sA = base + s * STAGE;
        const uint32_t sB = sA + TSZ;

        #pragma unroll
        for (int ks = 0; ks < 2; ks++) {
            uint32_t bh[4][2];
            #pragma unroll
            for (int np = 0; np < 2; np++) {
                uint32_t off = bbase[np] + ((uint32_t)(ks * 32 + bcol_add) ^ bsw[np]);
                ldsm_x4(bh[np*2][0], bh[np*2][1], bh[np*2+1][0], bh[np*2+1][1], sB + off);
            }
            #pragma unroll
            for (int mi = 0; mi < 4; mi++) {
                uint32_t off = abase[mi] + ((uint32_t)(ks * 32 + acol_add) ^ asw[mi]);
                uint32_t ah[4];
                ldsm_x4(ah[0], ah[1], ah[2], ah[3], sA + off);
                #pragma unroll
                for (int ni = 0; ni < 4; ni++)
                    mma16816(acc[mi][ni], ah, bh[ni]);
            }
        }
    }
    __syncthreads();

    // Epilogue
    const int colbase = blockIdx.y * 128 + wn * 32;
    #pragma unroll
    for (int mi = 0; mi < 4; mi++) {
        int r0 = m0 + wm * 64 + mi * 16 + g;
        #pragma unroll
        for (int ni = 0; ni < 4; ni++) {
            int c = colbase + ni * 8 + tig * 2;
            float v0 = acc[mi][ni][0], v1 = acc[mi][ni][1];
            float v2 = acc[mi][ni][2], v3 = acc[mi][ni][3];
            if (RELU) {
                v0 = fmaxf(v0, 0.f); v1 = fmaxf(v1, 0.f);
                v2 = fmaxf(v2, 0.f); v3 = fmaxf(v3, 0.f);
            }
            if (r0 < M)
                *(__half2*)(C + (size_t)r0 * NT + c) = __floats2half2_rn(v0, v1);
            if (r0 + 8 < M)
                *(__half2*)(C + (size_t)(r0 + 8) * NT + c) = __floats2half2_rn(v2, v3);
        }
    }
}

// ---------------------------------------------------------------------------
// Converters
// ---------------------------------------------------------------------------
__global__ void conv_feat(const float* __restrict__ F, __half* __restrict__ Ah, int n4) {
    int i = blockIdx.x * 256 + threadIdx.x;
    if (i >= n4) return;
    float4 v = ((const float4*)F)[i];
    __half2 h0 = __floats2half2_rn(v.x, v.y);
    __half2 h1 = __floats2half2_rn(v.z, v.w);
    *(uint2*)(Ah + (size_t)i * 4) = make_uint2(*(uint32_t*)&h0, *(uint32_t*)&h1);
}

__global__ void conv_w_all(const float* __restrict__ W1, const float* __restrict__ W2,
                           const float* __restrict__ W3, const float* __restrict__ W4,
                           __half* __restrict__ bw) {
    int i = blockIdx.x * 256 + threadIdx.x;
    if (i >= WTOT) return;
    float v;
    if (i < WOFF2) {                 // L1: stacked [Ws1; Wn1], K=256
        int t = i, j = t >> 8, k = t & 255;
        v = (j < 128) ? W1[(size_t)j * 512 + k] : W1[(size_t)(j - 128) * 512 + 256 + k];
    } else if (i < WOFF3) {          // L2: identity [128, 256]
        v = W2[i - WOFF2];
    } else if (i < WOFF4) {          // L3: identity
        v = W3[i - WOFF3];
    } else {                         // L4: stacked [Ws4; Wn4], K=128
        int t = i - WOFF4, j = t >> 7, k = t & 127;
        v = (j < 64) ? W4[(size_t)j * 256 + k] : W4[(size_t)(j - 64) * 256 + 128 + k];
    }
    bw[i] = __float2half_rn(v);
}

// ---------------------------------------------------------------------------
// mean_h: Hm[w,:] = (1/16) * sum_j H[neigh[w][j], :]   (128 cols fp16)
// ---------------------------------------------------------------------------
__global__ void mean_h(const __half* __restrict__ H, const int* __restrict__ neigh,
                       __half* __restrict__ Hm, int M) {
    const int w    = (blockIdx.x * blockDim.x + threadIdx.x) >> 5;
    const int lane = threadIdx.x & 31;
    if (w >= M) return;

    int nid = 0;
    if (lane < FANOUT) nid = neigh[(size_t)w * FANOUT + lane];

    float acc[4] = {};
    #pragma unroll
    for (int j = 0; j < FANOUT; j++) {
        int nj = __shfl_sync(0xffffffffu, nid, j);
        uint2 raw = *(const uint2*)(H + (size_t)nj * 128 + lane * 4);
        float2 f0 = __half22float2(*(__half2*)&raw.x);
        float2 f1 = __half22float2(*(__half2*)&raw.y);
        acc[0] += f0.x; acc[1] += f0.y; acc[2] += f1.x; acc[3] += f1.y;
    }
    const float inv = 1.0f / (float)FANOUT;
    __half2 o0 = __floats2half2_rn(acc[0] * inv, acc[1] * inv);
    __half2 o1 = __floats2half2_rn(acc[2] * inv, acc[3] * inv);
    *(uint2*)(Hm + (size_t)w * 128 + lane * 4) = make_uint2(*(uint32_t*)&o0, *(uint32_t*)&o1);
}

// ---------------------------------------------------------------------------
// agg_split (L1): relu(S + mean(P)) -> fp16 h (row stride 128); SP [M,256]
// ---------------------------------------------------------------------------
__global__ void agg_split(const __half* __restrict__ SP, const int* __restrict__ neigh,
                          __half* __restrict__ H, int M) {
    const int w    = (blockIdx.x * blockDim.x + threadIdx.x) >> 5;
    const int lane = threadIdx.x & 31;
    if (w >= M) return;

    int nid = 0;
    if (lane < FANOUT) nid = neigh[(size_t)w * FANOUT + lane];

    float acc[4] = {};
    #pragma unroll
    for (int j = 0; j < FANOUT; j++) {
        int nj = __shfl_sync(0xffffffffu, nid, j);
        uint2 raw = *(const uint2*)(SP + (size_t)nj * 256 + 128 + lane * 4);
        float2 f0 = __half22float2(*(__half2*)&raw.x);
        float2 f1 = __half22float2(*(__half2*)&raw.y);
        acc[0] += f0.x; acc[1] += f0.y; acc[2] += f1.x; acc[3] += f1.y;
    }
    uint2 sraw = *(const uint2*)(SP + (size_t)w * 256 + lane * 4);
    float2 s0 = __half22float2(*(__half2*)&sraw.x);
    float2 s1 = __half22float2(*(__half2*)&sraw.y);

    const float inv = 1.0f / (float)FANOUT;
    float r0 = fmaxf(fmaf(acc[0], inv, s0.x), 0.f);
    float r1 = fmaxf(fmaf(acc[1], inv, s0.y), 0.f);
    float r2 = fmaxf(fmaf(acc[2], inv, s1.x), 0.f);
    float r3 = fmaxf(fmaf(acc[3], inv, s1.y), 0.f);

    __half2 o0 = __floats2half2_rn(r0, r1);
    __half2 o1 = __floats2half2_rn(r2, r3);
    *(uint2*)(H + (size_t)w * 128 + lane * 4) = make_uint2(*(uint32_t*)&o0, *(uint32_t*)&o1);
}

// Final aggregation (L4): SP fp16 [M,128] (S=cols 0-63, P=64-127), fp32 out via nodes
__global__ void agg_final(const __half* __restrict__ SP, const int* __restrict__ neigh,
                          const int* __restrict__ nodes, float* __restrict__ out, int M) {
    const int w    = (blockIdx.x * blockDim.x + threadIdx.x) >> 5;
    const int lane = threadIdx.x & 31;
    if (w >= M) return;

    const int node = nodes[w];
    int nid = 0;
    if (lane < FANOUT) nid = neigh[(size_t)node * FANOUT + lane];

    float acc[2] = {};
    #pragma unroll
    for (int j = 0; j < FANOUT; j++) {
        int nj = __shfl_sync(0xffffffffu, nid, j);
        uint32_t raw = *(const uint32_t*)(SP + (size_t)nj * 128 + 64 + lane * 2);
        float2 f = __half22float2(*(__half2*)&raw);
        acc[0] += f.x; acc[1] += f.y;
    }
    uint32_t sraw = *(const uint32_t*)(SP + (size_t)node * 128 + lane * 2);
    float2 sv = __half22float2(*(__half2*)&sraw);

    const float inv = 1.0f / (float)FANOUT;
    float2 r;
    r.x = fmaxf(fmaf(acc[0], inv, sv.x), 0.f);
    r.y = fmaxf(fmaf(acc[1], inv, sv.y), 0.f);
    *(float2*)(out + (size_t)w * 64 + lane * 2) = r;
}

// ---------------------------------------------------------------------------

extern "C" void kernel_launch(void* const* d_in, const int* in_sizes, int n_in,
                              void* d_out, int out_size) {
    const float* features = (const float*)d_in[0];
    const float* W1       = (const float*)d_in[1];
    const float* W2       = (const float*)d_in[2];
    const float* W3       = (const float*)d_in[3];
    const float* W4       = (const float*)d_in[4];
    const int*   nodes    = (const int*)d_in[5];
    const int*   neigh    = (const int*)d_in[6];
    float*       out      = (float*)d_out;

    const int M = in_sizes[5];

    __half *sp, *ah, *hm, *bw;
    cudaGetSymbolAddress((void**)&sp, g_SP);
    cudaGetSymbolAddress((void**)&ah, g_Ah);
    cudaGetSymbolAddress((void**)&hm, g_Hm);
    cudaGetSymbolAddress((void**)&bw, g_Bw);

    constexpr int SMEM = 4 * 2 * 128 * 64 + 128;   // 4 stages x 2 tiles x 8KB + pad
    cudaFuncSetAttribute(gemm_mma<256, 256, false, false>,
                         cudaFuncAttributeMaxDynamicSharedMemorySize, SMEM);
    cudaFuncSetAttribute(gemm_mma<256, 128, true, true>,
                         cudaFuncAttributeMaxDynamicSharedMemorySize, SMEM);
    cudaFuncSetAttribute(gemm_mma<128, 128, false, false>,
                         cudaFuncAttributeMaxDynamicSharedMemorySize, SMEM);

    conv_w_all<<<(WTOT + 255) / 256, 256>>>(W1, W2, W3, W4, bw);
    conv_feat<<<(M * 64 + 255) / 256, 256>>>(features, ah, M * 64);

    const int gg = (M + 127) / 128;
    const int ab = (M + 7) / 8;

    // Layer 1: project-first (SP = [S|P]), then combine+relu
    gemm_mma<256, 256, false, false><<<dim3(gg, 2), 256, SMEM>>>(
        ah, nullptr, bw + WOFF1, sp, M);
    agg_split<<<ab, 256>>>(sp, neigh, ah, M);            // h1 -> g_Ah (stride 128)

    // Layer 2: gather-first, relu fused in GEMM
    mean_h<<<ab, 256>>>(ah, neigh, hm, M);
    gemm_mma<256, 128, true, true><<<dim3(gg, 1), 256, SMEM>>>(
        ah, hm, bw + WOFF2, sp, M);                      // h2 -> g_SP (stride 128)

    // Layer 3
    mean_h<<<ab, 256>>>(sp, neigh, hm, M);
    gemm_mma<256, 128, true, true><<<dim3(gg, 1), 256, SMEM>>>(
        sp, hm, bw + WOFF3, ah, M);                      // h3 -> g_Ah

    // Layer 4: project-first (SP4 = [S|P], 128 cols), then combine+relu via nodes
    gemm_mma<128, 128, false, false><<<dim3(gg, 1), 256, SMEM>>>(
        ah, nullptr, bw + WOFF4, sp, M);
    agg_final<<<ab, 256>>>(sp, neigh, nodes, out, M);
}

// round 15
// speedup vs baseline: 4.5369x; 1.0514x over previous
#include <cuda_runtime.h>
#include <cuda_fp16.h>
#include <cstdint>
#include <cstddef>

#define N_NODES 100000
#define FANOUT  16

// Global scratch (fp16)
__device__ __align__(16) __half g_SP[(size_t)N_NODES * 256];
__device__ __align__(16) __half g_Ah[(size_t)N_NODES * 256];
__device__ __align__(16) __half g_Hm[(size_t)N_NODES * 128];
// Packed weights (B layout), single fp16
#define WOFF1 0
#define WOFF2 65536
#define WOFF3 98304
#define WOFF4 131072
#define WTOT  147456
__device__ __align__(16) __half g_Bw[WTOT];

// ---------------------------------------------------------------------------
// Helpers
// ---------------------------------------------------------------------------
__device__ __forceinline__ uint32_t smem_u32(const void* p) {
    return (uint32_t)__cvta_generic_to_shared(p);
}
__device__ __forceinline__ void cp16(uint32_t dst, const void* src, int sz) {
    asm volatile("cp.async.cg.shared.global [%0], [%1], 16, %2;\n"
                 :: "r"(dst), "l"(src), "r"(sz));
}
__device__ __forceinline__ void ldsm_x4(uint32_t& r0, uint32_t& r1, uint32_t& r2,
                                        uint32_t& r3, uint32_t addr) {
    asm volatile("ldmatrix.sync.aligned.m8n8.x4.shared.b16 {%0,%1,%2,%3}, [%4];"
                 : "=r"(r0), "=r"(r1), "=r"(r2), "=r"(r3) : "r"(addr));
}
__device__ __forceinline__ void mma16816(float c[4], const uint32_t a[4], const uint32_t b[2]) {
    asm volatile(
        "mma.sync.aligned.m16n8k16.row.col.f32.f16.f16.f32 "
        "{%0,%1,%2,%3}, {%4,%5,%6,%7}, {%8,%9}, {%0,%1,%2,%3};\n"
        : "+f"(c[0]), "+f"(c[1]), "+f"(c[2]), "+f"(c[3])
        : "r"(a[0]), "r"(a[1]), "r"(a[2]), "r"(a[3]), "r"(b[0]), "r"(b[1]));
}

// ---------------------------------------------------------------------------
// fp16 tensor GEMM: C = act( A @ B^T )
// SPLITA: A k-cols [0,K/2) from A, [K/2,K) from A2 (both row stride 128).
// BM=128, BN=128, BK=64; 3-stage cp.async pipeline; SW128-swizzled 128B rows.
// ---------------------------------------------------------------------------
template<int K, int NT, bool RELU, bool SPLITA>
__global__ __launch_bounds__(256, 2)
void gemm_mma(const __half* __restrict__ A, const __half* __restrict__ A2,
              const __half* __restrict__ B, __half* __restrict__ C, int M) {
    constexpr int NC    = K / 64;            // k-chunks of 64
    constexpr int TSZ   = 128 * 128;         // bytes per tile (128 rows x 128B)
    constexpr int STAGE = 2 * TSZ;           // A, B
    constexpr int AST   = SPLITA ? 128 : K;  // A row stride (elements)

    extern __shared__ char dsm[];
    const uint32_t base = (smem_u32(dsm) + 127u) & ~127u;

    const int tid  = threadIdx.x;
    const int wid  = tid >> 5;
    const int lane = tid & 31;
    const int g    = lane >> 2;
    const int tig  = lane & 3;
    const int wm   = wid & 1;
    const int wn   = wid >> 1;
    const int m0   = blockIdx.x * 128;

    const __half* Bp = B + (size_t)blockIdx.y * 128 * K;

    // ldmatrix lane geometry
    const int arow_add = ((lane >> 3) & 1) * 8;
    const int acol_g   = (lane >> 4) & 1;        // 16B-granule offset within k-step
    const int brow_add = ((lane >> 4) & 1) * 8;
    const int bcol_g   = (lane >> 3) & 1;

    uint32_t abase[4], axor[4];
    #pragma unroll
    for (int mi = 0; mi < 4; mi++) {
        int r = wm * 64 + mi * 16 + arow_add + (lane & 7);
        abase[mi] = r * 128;
        axor[mi]  = r & 7;
    }
    uint32_t bbase[2], bxor[2];
    #pragma unroll
    for (int np = 0; np < 2; np++) {
        int r = wn * 32 + np * 16 + brow_add + (lane & 7);
        bbase[np] = r * 128;
        bxor[np]  = r & 7;
    }

    auto load_chunk = [&](int kc, int s) {
        const uint32_t sb = base + s * STAGE;
        const __half* Asrc = (SPLITA && kc >= NC / 2) ? A2 : A;
        const int acol = SPLITA ? ((kc & (NC / 2 - 1)) * 64) : kc * 64;
        #pragma unroll
        for (int u = tid; u < 1024; u += 256) {
            int row = u >> 3, c16 = u & 7;
            uint32_t off = row * 128 + ((c16 ^ (row & 7)) << 4);
            int gr = m0 + row;
            int szA = (gr < M) ? 16 : 0;
            cp16(sb + off,       Asrc + (size_t)gr * AST + acol + c16 * 8, szA);
            cp16(sb + TSZ + off, Bp + (size_t)row * K + kc * 64 + c16 * 8, 16);
        }
        asm volatile("cp.async.commit_group;" ::: "memory");
    };

    float acc[4][4][4] = {};

    load_chunk(0, 0);
    if (NC > 1) load_chunk(1, 1);

    #pragma unroll
    for (int kc = 0; kc < NC; kc++) {
        const int s = kc % 3;
        if (kc + 1 < NC) asm volatile("cp.async.wait_group 1;" ::: "memory");
        else             asm volatile("cp.async.wait_group 0;" ::: "memory");
        __syncthreads();
        if (kc + 2 < NC) load_chunk(kc + 2, (kc + 2) % 3);

        const uint32_t sA = base + s * STAGE;
        const uint32_t sB = sA + TSZ;

        #pragma unroll
        for (int ks = 0; ks < 4; ks++) {
            uint32_t bh[4][2];
            #pragma unroll
            for (int np = 0; np < 2; np++) {
                uint32_t c = (uint32_t)(ks * 2 + bcol_g);
                uint32_t off = bbase[np] + ((c ^ bxor[np]) << 4);
                ldsm_x4(bh[np*2][0], bh[np*2][1], bh[np*2+1][0], bh[np*2+1][1], sB + off);
            }
            #pragma unroll
            for (int mi = 0; mi < 4; mi++) {
                uint32_t c = (uint32_t)(ks * 2 + acol_g);
                uint32_t off = abase[mi] + ((c ^ axor[mi]) << 4);
                uint32_t ah[4];
                ldsm_x4(ah[0], ah[1], ah[2], ah[3], sA + off);
                #pragma unroll
                for (int ni = 0; ni < 4; ni++)
                    mma16816(acc[mi][ni], ah, bh[ni]);
            }
        }
    }

    // Epilogue
    const int colbase = blockIdx.y * 128 + wn * 32;
    #pragma unroll
    for (int mi = 0; mi < 4; mi++) {
        int r0 = m0 + wm * 64 + mi * 16 + g;
        #pragma unroll
        for (int ni = 0; ni < 4; ni++) {
            int c = colbase + ni * 8 + tig * 2;
            float v0 = acc[mi][ni][0], v1 = acc[mi][ni][1];
            float v2 = acc[mi][ni][2], v3 = acc[mi][ni][3];
            if (RELU) {
                v0 = fmaxf(v0, 0.f); v1 = fmaxf(v1, 0.f);
                v2 = fmaxf(v2, 0.f); v3 = fmaxf(v3, 0.f);
            }
            if (r0 < M)
                *(__half2*)(C + (size_t)r0 * NT + c) = __floats2half2_rn(v0, v1);
            if (r0 + 8 < M)
                *(__half2*)(C + (size_t)(r0 + 8) * NT + c) = __floats2half2_rn(v2, v3);
        }
    }
}

// ---------------------------------------------------------------------------
// Converters
// ---------------------------------------------------------------------------
__global__ void conv_feat(const float* __restrict__ F, __half* __restrict__ Ah, int n4) {
    int i = blockIdx.x * 256 + threadIdx.x;
    if (i >= n4) return;
    float4 v = ((const float4*)F)[i];
    __half2 h0 = __floats2half2_rn(v.x, v.y);
    __half2 h1 = __floats2half2_rn(v.z, v.w);
    *(uint2*)(Ah + (size_t)i * 4) = make_uint2(*(uint32_t*)&h0, *(uint32_t*)&h1);
}

__global__ void conv_w_all(const float* __restrict__ W1, const float* __restrict__ W2,
                           const float* __restrict__ W3, const float* __restrict__ W4,
                           __half* __restrict__ bw) {
    int i = blockIdx.x * 256 + threadIdx.x;
    if (i >= WTOT) return;
    float v;
    if (i < WOFF2) {                 // L1: stacked [Ws1; Wn1], K=256
        int t = i, j = t >> 8, k = t & 255;
        v = (j < 128) ? W1[(size_t)j * 512 + k] : W1[(size_t)(j - 128) * 512 + 256 + k];
    } else if (i < WOFF3) {          // L2: identity [128, 256]
        v = W2[i - WOFF2];
    } else if (i < WOFF4) {          // L3: identity
        v = W3[i - WOFF3];
    } else {                         // L4: stacked [Ws4; Wn4], K=128
        int t = i - WOFF4, j = t >> 7, k = t & 127;
        v = (j < 64) ? W4[(size_t)j * 256 + k] : W4[(size_t)(j - 64) * 256 + 128 + k];
    }
    bw[i] = __float2half_rn(v);
}

// ---------------------------------------------------------------------------
// mean_h: Hm[w,:] = (1/16) * sum_j H[neigh[w][j], :]   (128 cols fp16)
// Pairwise fp16 pre-add (j, j+8), then fp32 accumulate.
// ---------------------------------------------------------------------------
__global__ void mean_h(const __half* __restrict__ H, const int* __restrict__ neigh,
                       __half* __restrict__ Hm, int M) {
    const int w    = (blockIdx.x * blockDim.x + threadIdx.x) >> 5;
    const int lane = threadIdx.x & 31;
    if (w >= M) return;

    int nid = 0;
    if (lane < FANOUT) nid = neigh[(size_t)w * FANOUT + lane];

    float acc[4] = {};
    #pragma unroll
    for (int p = 0; p < 8; p++) {
        int nj0 = __shfl_sync(0xffffffffu, nid, p);
        int nj1 = __shfl_sync(0xffffffffu, nid, p + 8);
        uint2 a = *(const uint2*)(H + (size_t)nj0 * 128 + lane * 4);
        uint2 b = *(const uint2*)(H + (size_t)nj1 * 128 + lane * 4);
        __half2 s0 = __hadd2(*(__half2*)&a.x, *(__half2*)&b.x);
        __half2 s1 = __hadd2(*(__half2*)&a.y, *(__half2*)&b.y);
        float2 f0 = __half22float2(s0);
        float2 f1 = __half22float2(s1);
        acc[0] += f0.x; acc[1] += f0.y; acc[2] += f1.x; acc[3] += f1.y;
    }
    const float inv = 1.0f / (float)FANOUT;
    __half2 o0 = __floats2half2_rn(acc[0] * inv, acc[1] * inv);
    __half2 o1 = __floats2half2_rn(acc[2] * inv, acc[3] * inv);
    *(uint2*)(Hm + (size_t)w * 128 + lane * 4) = make_uint2(*(uint32_t*)&o0, *(uint32_t*)&o1);
}

// ---------------------------------------------------------------------------
// agg_split (L1): relu(S + mean(P)) -> fp16 h (row stride 128); SP [M,256]
// ---------------------------------------------------------------------------
__global__ void agg_split(const __half* __restrict__ SP, const int* __restrict__ neigh,
                          __half* __restrict__ H, int M) {
    const int w    = (blockIdx.x * blockDim.x + threadIdx.x) >> 5;
    const int lane = threadIdx.x & 31;
    if (w >= M) return;

    int nid = 0;
    if (lane < FANOUT) nid = neigh[(size_t)w * FANOUT + lane];

    float acc[4] = {};
    #pragma unroll
    for (int p = 0; p < 8; p++) {
        int nj0 = __shfl_sync(0xffffffffu, nid, p);
        int nj1 = __shfl_sync(0xffffffffu, nid, p + 8);
        uint2 a = *(const uint2*)(SP + (size_t)nj0 * 256 + 128 + lane * 4);
        uint2 b = *(const uint2*)(SP + (size_t)nj1 * 256 + 128 + lane * 4);
        __half2 s0 = __hadd2(*(__half2*)&a.x, *(__half2*)&b.x);
        __half2 s1 = __hadd2(*(__half2*)&a.y, *(__half2*)&b.y);
        float2 f0 = __half22float2(s0);
        float2 f1 = __half22float2(s1);
        acc[0] += f0.x; acc[1] += f0.y; acc[2] += f1.x; acc[3] += f1.y;
    }
    uint2 sraw = *(const uint2*)(SP + (size_t)w * 256 + lane * 4);
    float2 s0 = __half22float2(*(__half2*)&sraw.x);
    float2 s1 = __half22float2(*(__half2*)&sraw.y);

    const float inv = 1.0f / (float)FANOUT;
    float r0 = fmaxf(fmaf(acc[0], inv, s0.x), 0.f);
    float r1 = fmaxf(fmaf(acc[1], inv, s0.y), 0.f);
    float r2 = fmaxf(fmaf(acc[2], inv, s1.x), 0.f);
    float r3 = fmaxf(fmaf(acc[3], inv, s1.y), 0.f);

    __half2 o0 = __floats2half2_rn(r0, r1);
    __half2 o1 = __floats2half2_rn(r2, r3);
    *(uint2*)(H + (size_t)w * 128 + lane * 4) = make_uint2(*(uint32_t*)&o0, *(uint32_t*)&o1);
}

// Final aggregation (L4): SP fp16 [M,128] (S=cols 0-63, P=64-127), fp32 out via nodes
__global__ void agg_final(const __half* __restrict__ SP, const int* __restrict__ neigh,
                          const int* __restrict__ nodes, float* __restrict__ out, int M) {
    const int w    = (blockIdx.x * blockDim.x + threadIdx.x) >> 5;
    const int lane = threadIdx.x & 31;
    if (w >= M) return;

    const int node = nodes[w];
    int nid = 0;
    if (lane < FANOUT) nid = neigh[(size_t)node * FANOUT + lane];

    float acc[2] = {};
    #pragma unroll
    for (int p = 0; p < 8; p++) {
        int nj0 = __shfl_sync(0xffffffffu, nid, p);
        int nj1 = __shfl_sync(0xffffffffu, nid, p + 8);
        uint32_t a = *(const uint32_t*)(SP + (size_t)nj0 * 128 + 64 + lane * 2);
        uint32_t b = *(const uint32_t*)(SP + (size_t)nj1 * 128 + 64 + lane * 2);
        __half2 s = __hadd2(*(__half2*)&a, *(__half2*)&b);
        float2 f = __half22float2(s);
        acc[0] += f.x; acc[1] += f.y;
    }
    uint32_t sraw = *(const uint32_t*)(SP + (size_t)node * 128 + lane * 2);
    float2 sv = __half22float2(*(__half2*)&sraw);

    const float inv = 1.0f / (float)FANOUT;
    float2 r;
    r.x = fmaxf(fmaf(acc[0], inv, sv.x), 0.f);
    r.y = fmaxf(fmaf(acc[1], inv, sv.y), 0.f);
    *(float2*)(out + (size_t)w * 64 + lane * 2) = r;
}

// ---------------------------------------------------------------------------

extern "C" void kernel_launch(void* const* d_in, const int* in_sizes, int n_in,
                              void* d_out, int out_size) {
    const float* features = (const float*)d_in[0];
    const float* W1       = (const float*)d_in[1];
    const float* W2       = (const float*)d_in[2];
    const float* W3       = (const float*)d_in[3];
    const float* W4       = (const float*)d_in[4];
    const int*   nodes    = (const int*)d_in[5];
    const int*   neigh    = (const int*)d_in[6];
    float*       out      = (float*)d_out;

    const int M = in_sizes[5];

    __half *sp, *ah, *hm, *bw;
    cudaGetSymbolAddress((void**)&sp, g_SP);
    cudaGetSymbolAddress((void**)&ah, g_Ah);
    cudaGetSymbolAddress((void**)&hm, g_Hm);
    cudaGetSymbolAddress((void**)&bw, g_Bw);

    constexpr int SMEM = 3 * 2 * 128 * 128 + 128;   // 3 stages x 2 tiles x 16KB + pad
    cudaFuncSetAttribute(gemm_mma<256, 256, false, false>,
                         cudaFuncAttributeMaxDynamicSharedMemorySize, SMEM);
    cudaFuncSetAttribute(gemm_mma<256, 128, true, true>,
                         cudaFuncAttributeMaxDynamicSharedMemorySize, SMEM);
    cudaFuncSetAttribute(gemm_mma<128, 128, false, false>,
                         cudaFuncAttributeMaxDynamicSharedMemorySize, SMEM);

    conv_w_all<<<(WTOT + 255) / 256, 256>>>(W1, W2, W3, W4, bw);
    conv_feat<<<(M * 64 + 255) / 256, 256>>>(features, ah, M * 64);

    const int gg = (M + 127) / 128;
    const int ab = (M + 7) / 8;

    // Layer 1: project-first (SP = [S|P]), then combine+relu
    gemm_mma<256, 256, false, false><<<dim3(gg, 2), 256, SMEM>>>(
        ah, nullptr, bw + WOFF1, sp, M);
    agg_split<<<ab, 256>>>(sp, neigh, ah, M);            // h1 -> g_Ah (stride 128)

    // Layer 2: gather-first, relu fused in GEMM
    mean_h<<<ab, 256>>>(ah, neigh, hm, M);
    gemm_mma<256, 128, true, true><<<dim3(gg, 1), 256, SMEM>>>(
        ah, hm, bw + WOFF2, sp, M);                      // h2 -> g_SP (stride 128)

    // Layer 3
    mean_h<<<ab, 256>>>(sp, neigh, hm, M);
    gemm_mma<256, 128, true, true><<<dim3(gg, 1), 256, SMEM>>>(
        sp, hm, bw + WOFF3, ah, M);                      // h3 -> g_Ah

    // Layer 4: project-first (SP4 = [S|P], 128 cols), then combine+relu via nodes
    gemm_mma<128, 128, false, false><<<dim3(gg, 1), 256, SMEM>>>(
        ah, nullptr, bw + WOFF4, sp, M);
    agg_final<<<ab, 256>>>(sp, neigh, nodes, out, M);
}